// round 6
// baseline (speedup 1.0000x reference)
#include <cuda_runtime.h>
#include <cstdint>

#define N_NODES 100000
#define N_EDGES 1600000
#define N_GRAPHS 512
#define NHID 128
#define NLAYER 3

typedef unsigned long long ull;

// ---------------- scratch (static device arrays; no allocation) -------------
__device__ __align__(16) float g_z[(size_t)N_NODES * NHID];   // agg buffer
__device__ __align__(16) float g_h[(size_t)N_NODES * NHID];   // layer out
__device__ __align__(16) float g_pool[N_GRAPHS * NHID];
__device__ int g_idx64;   // 1 if index tensors are int64, 0 if int32

// ---------------- helpers ---------------------------------------------------
__device__ __forceinline__ void red_add_v4(float* addr, float4 v) {
    asm volatile("red.global.add.v4.f32 [%0], {%1,%2,%3,%4};"
                 :: "l"(addr), "f"(v.x), "f"(v.y), "f"(v.z), "f"(v.w)
                 : "memory");
}

// packed f32x2 FMA: d = a*b + d (elementwise on 2 packed floats)
__device__ __forceinline__ void fma2(ull& d, ull a, ull b) {
    asm("fma.rn.f32x2 %0, %1, %2, %3;" : "=l"(d) : "l"(a), "l"(b), "l"(d));
}

__device__ __forceinline__ float f32x2_hsum(ull v) {
    float lo = __uint_as_float((unsigned)(v & 0xffffffffu));
    float hi = __uint_as_float((unsigned)(v >> 32));
    return lo + hi;
}

// ---------------- kernels ---------------------------------------------------

// Detect index width from edge_index (unsorted node ids << 2^31):
// int64 layout -> every odd 32-bit word is zero.
__global__ void detect_kernel(const int* __restrict__ ei_raw) {
    if (threadIdx.x == 0) {
        int odd = 0;
        for (int i = 0; i < 64; i++) odd |= ei_raw[2 * i + 1];
        g_idx64 = (odd == 0) ? 1 : 0;
    }
}

__global__ void zero_kernel(float4* __restrict__ dst, int n4) {
    int i = blockIdx.x * blockDim.x + threadIdx.x;
    if (i < n4) dst[i] = make_float4(0.f, 0.f, 0.f, 0.f);
}

// agg[dst] += h[src]; one warp per edge, one float4 lane per thread
__global__ void scatter_kernel(const float* __restrict__ h,
                               const void* __restrict__ ei_raw,
                               float* __restrict__ agg) {
    int t = blockIdx.x * blockDim.x + threadIdx.x;   // < N_EDGES*32
    int e = t >> 5;
    int c = (t & 31) << 2;
    int s, d;
    if (g_idx64) {
        const long long* ei = (const long long*)ei_raw;
        s = (int)ei[e];
        d = (int)ei[N_EDGES + e];
    } else {
        const int* ei = (const int*)ei_raw;
        s = ei[e];
        d = ei[N_EDGES + e];
    }
    float4 v = *(const float4*)(h + (size_t)s * NHID + c);
    red_add_v4(agg + (size_t)d * NHID + c, v);
}

// ---------------- fused 2-layer MLP -----------------------------------------
// hout = relu( relu((agg+h)@W1^T+b1) @ W2^T + b2 )
// 256 threads, 64-row x 128-col tile, thread tile 4 rows x 8 cols.
// Columns per thread: {tx, tx+16, ..., tx+112} (tx = tid & 15): phase bank
// stride SP=132 == 4 (mod 32) -> conflict-free LDS.128 of W rows.
// Inner product uses packed f32x2 FMA over k-pairs (2x fp32 issue rate);
// 2-wide partial accumulators, horizontal-summed (+bias) in the epilogue.
// One weight matrix staged at a time -> 103 KB smem, 2 CTAs/SM.
#define SP 132
#define MLP_SMEM_FLOATS (128*SP + 64*SP + 256)
#define MLP_SMEM_BYTES  (MLP_SMEM_FLOATS * 4)

__device__ __forceinline__ void gemm_tile_f32x2(const float* __restrict__ Ws,
                                                const float* __restrict__ zt,
                                                ull acc2[4][8], int tx, int r0) {
#pragma unroll
    for (int i = 0; i < 4; i++)
#pragma unroll
        for (int c = 0; c < 8; c++) acc2[i][c] = 0ULL;

#pragma unroll 4
    for (int k4 = 0; k4 < 32; k4++) {
        ull wv[8][2];
#pragma unroll
        for (int c = 0; c < 8; c++) {
            double2 t = *(const double2*)(Ws + (tx + 16 * c) * SP + k4 * 4);
            wv[c][0] = __double_as_longlong(t.x);
            wv[c][1] = __double_as_longlong(t.y);
        }
        ull zv[4][2];
#pragma unroll
        for (int i = 0; i < 4; i++) {
            double2 t = *(const double2*)(zt + (r0 + i) * SP + k4 * 4);
            zv[i][0] = __double_as_longlong(t.x);
            zv[i][1] = __double_as_longlong(t.y);
        }
#pragma unroll
        for (int i = 0; i < 4; i++)
#pragma unroll
            for (int c = 0; c < 8; c++) {
                fma2(acc2[i][c], zv[i][0], wv[c][0]);
                fma2(acc2[i][c], zv[i][1], wv[c][1]);
            }
    }
}

__global__ __launch_bounds__(256, 2)
void mlp_kernel(const float* __restrict__ agg, const float* __restrict__ hin,
                const float* __restrict__ W1, const float* __restrict__ b1,
                const float* __restrict__ W2, const float* __restrict__ b2,
                float* __restrict__ hout) {
    extern __shared__ float sm[];
    float* Ws  = sm;                 // [128][SP]  (W1, then W2)
    float* zt  = sm + 128 * SP;      // [64][SP]   (z, then t)
    float* b1s = sm + 128 * SP + 64 * SP;
    float* b2s = b1s + 128;

    const int tid = threadIdx.x;
    const int tx = tid & 15;         // 16 col-threads, 8 cols each
    const int ty = tid >> 4;         // 16 row-groups, 4 rows each
    const int r0 = ty * 4;
    const int row0 = blockIdx.x * 64;

    // stage W1 + biases
    {
        const float4* Wv = (const float4*)W1;
        for (int i = tid; i < 4096; i += 256) {
            int r = i >> 5, c4 = i & 31;
            *(float4*)(Ws + r * SP + c4 * 4) = Wv[i];
        }
        if (tid < 128) { b1s[tid] = b1[tid]; b2s[tid] = b2[tid]; }
    }
    // stage z = agg + h
    for (int i = tid; i < 64 * 32; i += 256) {
        int r = i >> 5, c4 = i & 31;
        int row = row0 + r;
        float4 v = make_float4(0.f, 0.f, 0.f, 0.f);
        if (row < N_NODES) {
            float4 a = *(const float4*)(agg + (size_t)row * NHID + c4 * 4);
            float4 h = *(const float4*)(hin + (size_t)row * NHID + c4 * 4);
            v = make_float4(a.x + h.x, a.y + h.y, a.z + h.z, a.w + h.w);
        }
        *(float4*)(zt + r * SP + c4 * 4) = v;
    }
    __syncthreads();

    ull acc2[4][8];
    float tvals[4][8];

    // ---- GEMM1 + relu ----
    gemm_tile_f32x2(Ws, zt, acc2, tx, r0);
#pragma unroll
    for (int i = 0; i < 4; i++)
#pragma unroll
        for (int c = 0; c < 8; c++)
            tvals[i][c] = fmaxf(f32x2_hsum(acc2[i][c]) + b1s[tx + 16 * c], 0.f);

    __syncthreads();   // all GEMM1 reads of Ws/zt done

    // write t over zt; restage Ws with W2
#pragma unroll
    for (int i = 0; i < 4; i++)
#pragma unroll
        for (int c = 0; c < 8; c++)
            zt[(r0 + i) * SP + tx + 16 * c] = tvals[i][c];
    {
        const float4* Wv = (const float4*)W2;
        for (int i = tid; i < 4096; i += 256) {
            int r = i >> 5, c4 = i & 31;
            *(float4*)(Ws + r * SP + c4 * 4) = Wv[i];
        }
    }
    __syncthreads();

    // ---- GEMM2 + relu + store ----
    gemm_tile_f32x2(Ws, zt, acc2, tx, r0);
#pragma unroll
    for (int i = 0; i < 4; i++) {
        int row = row0 + r0 + i;
        if (row < N_NODES) {
#pragma unroll
            for (int c = 0; c < 8; c++)
                hout[(size_t)row * NHID + tx + 16 * c] =
                    fmaxf(f32x2_hsum(acc2[i][c]) + b2s[tx + 16 * c], 0.f);
        }
    }
}

__global__ void pool_zero_kernel() {
    int i = blockIdx.x * blockDim.x + threadIdx.x;
    if (i < N_GRAPHS * NHID) g_pool[i] = 0.f;
}

__global__ void pool_kernel(const float* __restrict__ h,
                            const void* __restrict__ batch_raw) {
    int t = blockIdx.x * blockDim.x + threadIdx.x;   // < N_NODES*32
    int n = t >> 5;
    int c = (t & 31) << 2;
    int g;
    if (g_idx64) g = (int)((const long long*)batch_raw)[n];
    else         g = ((const int*)batch_raw)[n];
    float4 v = *(const float4*)(h + (size_t)n * NHID + c);
    red_add_v4(g_pool + g * NHID + c, v);
}

__global__ void lsm_kernel(float* __restrict__ out) {
    int r = blockIdx.x;
    int c = threadIdx.x;
    int w = c >> 5, lane = c & 31;
    __shared__ float smax[4], ssum[4];

    float v = g_pool[r * NHID + c];

    float m = v;
#pragma unroll
    for (int off = 16; off > 0; off >>= 1)
        m = fmaxf(m, __shfl_xor_sync(0xffffffffu, m, off));
    if (lane == 0) smax[w] = m;
    __syncthreads();
    m = fmaxf(fmaxf(smax[0], smax[1]), fmaxf(smax[2], smax[3]));

    float e = expf(v - m);
    float s = e;
#pragma unroll
    for (int off = 16; off > 0; off >>= 1)
        s += __shfl_xor_sync(0xffffffffu, s, off);
    if (lane == 0) ssum[w] = s;
    __syncthreads();
    s = ssum[0] + ssum[1] + ssum[2] + ssum[3];

    out[r * NHID + c] = (v - m) - logf(s);
}

// ---------------- launch -----------------------------------------------------
extern "C" void kernel_launch(void* const* d_in, const int* in_sizes, int n_in,
                              void* d_out, int out_size) {
    // Resolve inputs by element count (robust to metadata ordering).
    const float* x     = nullptr;
    const void*  ei    = nullptr;
    const void*  batch = nullptr;
    const float *W1 = nullptr, *b1 = nullptr, *W2 = nullptr, *b2 = nullptr;

    for (int i = 0; i < n_in; i++) {
        int sz = in_sizes[i];
        if (sz == N_NODES * NHID)            x = (const float*)d_in[i];
        else if (sz == 2 * N_EDGES)          ei = d_in[i];
        else if (sz == N_NODES)              batch = d_in[i];
        else if (sz == NLAYER * NHID * NHID) { if (!W1) W1 = (const float*)d_in[i]; else W2 = (const float*)d_in[i]; }
        else if (sz == NLAYER * NHID)        { if (!b1) b1 = (const float*)d_in[i]; else b2 = (const float*)d_in[i]; }
    }
    float* out = (float*)d_out;

    float *zp = nullptr, *hp = nullptr;
    cudaGetSymbolAddress((void**)&zp, g_z);
    cudaGetSymbolAddress((void**)&hp, g_h);

    cudaFuncSetAttribute(mlp_kernel, cudaFuncAttributeMaxDynamicSharedMemorySize, MLP_SMEM_BYTES);

    const int n4 = N_NODES * NHID / 4;               // 3,200,000
    const int zero_blocks    = n4 / 256;             // 12500
    const int scatter_blocks = (N_EDGES * 32) / 256; // 200000
    const int mlp_blocks     = (N_NODES + 63) / 64;  // 1563
    const int pool_blocks    = (N_NODES * 32) / 256; // 12500

    detect_kernel<<<1, 32>>>((const int*)ei);

    const float* hin = x;
    for (int l = 0; l < NLAYER; l++) {
        zero_kernel<<<zero_blocks, 256>>>((float4*)zp, n4);
        scatter_kernel<<<scatter_blocks, 256>>>(hin, ei, zp);
        mlp_kernel<<<mlp_blocks, 256, MLP_SMEM_BYTES>>>(
            zp, hin, W1 + l * NHID * NHID, b1 + l * NHID,
            W2 + l * NHID * NHID, b2 + l * NHID, hp);
        hin = hp;
    }

    pool_zero_kernel<<<(N_GRAPHS * NHID + 255) / 256, 256>>>();
    pool_kernel<<<pool_blocks, 256>>>(hp, batch);
    lsm_kernel<<<N_GRAPHS, NHID>>>(out);
}

// round 7
// speedup vs baseline: 1.4798x; 1.4798x over previous
#include <cuda_runtime.h>
#include <cstdint>

#define N_NODES 100000
#define N_EDGES 1600000
#define N_GRAPHS 512
#define NHID 128
#define NLAYER 3

typedef unsigned long long ull;

// ---------------- scratch (static device arrays; no allocation) -------------
__device__ __align__(16) float g_z[(size_t)N_NODES * NHID];   // z = h + agg
__device__ __align__(16) float g_h[(size_t)N_NODES * NHID];   // layer out
__device__ __align__(16) float g_pool[N_GRAPHS * NHID];
__device__ int g_idx64;                 // 1 if index tensors are int64
__device__ int g_deg[N_NODES];          // degree histogram / cursor
__device__ int g_rowoff[N_NODES + 1];   // CSR row offsets (by dst)
__device__ int g_csr_src[N_EDGES];      // src ids grouped by dst
__device__ int g_bsum[128];             // scan block sums

// ---------------- helpers ---------------------------------------------------
__device__ __forceinline__ void red_add_v4(float* addr, float4 v) {
    asm volatile("red.global.add.v4.f32 [%0], {%1,%2,%3,%4};"
                 :: "l"(addr), "f"(v.x), "f"(v.y), "f"(v.z), "f"(v.w)
                 : "memory");
}

__device__ __forceinline__ void fma2(ull& d, ull a, ull b) {
    asm("fma.rn.f32x2 %0, %1, %2, %3;" : "=l"(d) : "l"(a), "l"(b), "l"(d));
}

__device__ __forceinline__ float f32x2_hsum(ull v) {
    float lo = __uint_as_float((unsigned)(v & 0xffffffffu));
    float hi = __uint_as_float((unsigned)(v >> 32));
    return lo + hi;
}

__device__ __forceinline__ int load_idx(const void* raw, int i, int idx64) {
    return idx64 ? (int)((const long long*)raw)[i] : ((const int*)raw)[i];
}

// ---------------- index-width detection --------------------------------------
__global__ void detect_kernel(const int* __restrict__ ei_raw) {
    if (threadIdx.x == 0) {
        int odd = 0;
        for (int i = 0; i < 64; i++) odd |= ei_raw[2 * i + 1];
        g_idx64 = (odd == 0) ? 1 : 0;
    }
}

// ---------------- CSR build (once per launch) --------------------------------
__global__ void deg_zero_kernel() {
    int i = blockIdx.x * blockDim.x + threadIdx.x;
    if (i < N_NODES) g_deg[i] = 0;
}

__global__ void hist_kernel(const void* __restrict__ ei_raw) {
    int e = blockIdx.x * blockDim.x + threadIdx.x;
    if (e < N_EDGES) {
        int d = load_idx(ei_raw, N_EDGES + e, g_idx64);
        atomicAdd(&g_deg[d], 1);
    }
}

// exclusive scan of g_deg into g_rowoff, 1024 elems per block
__global__ void scan1_kernel() {
    __shared__ int wsum[32];
    int b = blockIdx.x, t = threadIdx.x;
    int gi = b * 1024 + t;
    int v = (gi < N_NODES) ? g_deg[gi] : 0;
    int lane = t & 31, w = t >> 5;
    // warp inclusive scan
    int s = v;
#pragma unroll
    for (int o = 1; o < 32; o <<= 1) {
        int u = __shfl_up_sync(0xffffffffu, s, o);
        if (lane >= o) s += u;
    }
    if (lane == 31) wsum[w] = s;
    __syncthreads();
    if (w == 0) {
        int ws = (lane < 32) ? wsum[lane] : 0;
#pragma unroll
        for (int o = 1; o < 32; o <<= 1) {
            int u = __shfl_up_sync(0xffffffffu, ws, o);
            if (lane >= o) ws += u;
        }
        wsum[lane] = ws;
    }
    __syncthreads();
    int excl = s - v + (w > 0 ? wsum[w - 1] : 0);
    if (gi < N_NODES) g_rowoff[gi] = excl;
    if (t == 1023) g_bsum[b] = excl + v;   // block total
}

__global__ void scan2_kernel(int nblocks) {
    // single block of 128 threads, serial-ish scan of nblocks (<=98) sums
    if (threadIdx.x == 0) {
        int acc = 0;
        for (int i = 0; i < nblocks; i++) {
            int t = g_bsum[i];
            g_bsum[i] = acc;
            acc += t;
        }
        g_rowoff[N_NODES] = N_EDGES;
    }
}

__global__ void scan3_kernel() {
    int i = blockIdx.x * blockDim.x + threadIdx.x;
    if (i < N_NODES) g_rowoff[i] += g_bsum[i >> 10];
    if (i < N_NODES) g_deg[i] = 0;   // reset as fill cursor
}

__global__ void fill_kernel(const void* __restrict__ ei_raw) {
    int e = blockIdx.x * blockDim.x + threadIdx.x;
    if (e < N_EDGES) {
        int idx64 = g_idx64;
        int s = load_idx(ei_raw, e, idx64);
        int d = load_idx(ei_raw, N_EDGES + e, idx64);
        int pos = g_rowoff[d] + atomicAdd(&g_deg[d], 1);
        g_csr_src[pos] = s;
    }
}

// ---------------- per-layer aggregation: z = h + sum_{src in N(dst)} h[src] --
// one warp per node; lane owns 4 columns (float4).
__global__ __launch_bounds__(256, 8)
void gin_agg_kernel(const float* __restrict__ h, float* __restrict__ z) {
    int gw = (blockIdx.x * blockDim.x + threadIdx.x) >> 5;
    if (gw >= N_NODES) return;
    int lane = threadIdx.x & 31;
    int c = lane << 2;

    float4 acc = *(const float4*)(h + (size_t)gw * NHID + c);
    int beg = g_rowoff[gw], end = g_rowoff[gw + 1];

    for (int i = beg; i < end; i += 32) {
        int cnt = min(32, end - i);
        int s = (lane < cnt) ? g_csr_src[i + lane] : 0;
        for (int j = 0; j < cnt; j++) {
            int sj = __shfl_sync(0xffffffffu, s, j);
            float4 v = *(const float4*)(h + (size_t)sj * NHID + c);
            acc.x += v.x; acc.y += v.y; acc.z += v.z; acc.w += v.w;
        }
    }
    *(float4*)(z + (size_t)gw * NHID + c) = acc;
}

// ---------------- fused 2-layer MLP ------------------------------------------
#define SP 132
#define MLP_SMEM_FLOATS (128*SP + 64*SP + 256)
#define MLP_SMEM_BYTES  (MLP_SMEM_FLOATS * 4)

__device__ __forceinline__ void gemm_tile_f32x2(const float* __restrict__ Ws,
                                                const float* __restrict__ zt,
                                                ull acc2[4][8], int tx, int r0) {
#pragma unroll
    for (int i = 0; i < 4; i++)
#pragma unroll
        for (int c = 0; c < 8; c++) acc2[i][c] = 0ULL;

#pragma unroll 4
    for (int k4 = 0; k4 < 32; k4++) {
        ull wv[8][2];
#pragma unroll
        for (int c = 0; c < 8; c++) {
            double2 t = *(const double2*)(Ws + (tx + 16 * c) * SP + k4 * 4);
            wv[c][0] = __double_as_longlong(t.x);
            wv[c][1] = __double_as_longlong(t.y);
        }
        ull zv[4][2];
#pragma unroll
        for (int i = 0; i < 4; i++) {
            double2 t = *(const double2*)(zt + (r0 + i) * SP + k4 * 4);
            zv[i][0] = __double_as_longlong(t.x);
            zv[i][1] = __double_as_longlong(t.y);
        }
#pragma unroll
        for (int i = 0; i < 4; i++)
#pragma unroll
            for (int c = 0; c < 8; c++) {
                fma2(acc2[i][c], zv[i][0], wv[c][0]);
                fma2(acc2[i][c], zv[i][1], wv[c][1]);
            }
    }
}

__global__ __launch_bounds__(256, 2)
void mlp_kernel(const float* __restrict__ zin,
                const float* __restrict__ W1, const float* __restrict__ b1,
                const float* __restrict__ W2, const float* __restrict__ b2,
                float* __restrict__ hout) {
    extern __shared__ float sm[];
    float* Ws  = sm;                 // [128][SP]  (W1, then W2)
    float* zt  = sm + 128 * SP;      // [64][SP]   (z, then t)
    float* b1s = sm + 128 * SP + 64 * SP;
    float* b2s = b1s + 128;

    const int tid = threadIdx.x;
    const int tx = tid & 15;
    const int ty = tid >> 4;
    const int r0 = ty * 4;
    const int row0 = blockIdx.x * 64;

    {
        const float4* Wv = (const float4*)W1;
        for (int i = tid; i < 4096; i += 256) {
            int r = i >> 5, c4 = i & 31;
            *(float4*)(Ws + r * SP + c4 * 4) = Wv[i];
        }
        if (tid < 128) { b1s[tid] = b1[tid]; b2s[tid] = b2[tid]; }
    }
    for (int i = tid; i < 64 * 32; i += 256) {
        int r = i >> 5, c4 = i & 31;
        int row = row0 + r;
        float4 v = make_float4(0.f, 0.f, 0.f, 0.f);
        if (row < N_NODES) v = *(const float4*)(zin + (size_t)row * NHID + c4 * 4);
        *(float4*)(zt + r * SP + c4 * 4) = v;
    }
    __syncthreads();

    ull acc2[4][8];
    float tvals[4][8];

    gemm_tile_f32x2(Ws, zt, acc2, tx, r0);
#pragma unroll
    for (int i = 0; i < 4; i++)
#pragma unroll
        for (int c = 0; c < 8; c++)
            tvals[i][c] = fmaxf(f32x2_hsum(acc2[i][c]) + b1s[tx + 16 * c], 0.f);

    __syncthreads();

#pragma unroll
    for (int i = 0; i < 4; i++)
#pragma unroll
        for (int c = 0; c < 8; c++)
            zt[(r0 + i) * SP + tx + 16 * c] = tvals[i][c];
    {
        const float4* Wv = (const float4*)W2;
        for (int i = tid; i < 4096; i += 256) {
            int r = i >> 5, c4 = i & 31;
            *(float4*)(Ws + r * SP + c4 * 4) = Wv[i];
        }
    }
    __syncthreads();

    gemm_tile_f32x2(Ws, zt, acc2, tx, r0);
#pragma unroll
    for (int i = 0; i < 4; i++) {
        int row = row0 + r0 + i;
        if (row < N_NODES) {
#pragma unroll
            for (int c = 0; c < 8; c++)
                hout[(size_t)row * NHID + tx + 16 * c] =
                    fmaxf(f32x2_hsum(acc2[i][c]) + b2s[tx + 16 * c], 0.f);
        }
    }
}

// ---------------- pooling + log_softmax --------------------------------------
__global__ void pool_zero_kernel() {
    int i = blockIdx.x * blockDim.x + threadIdx.x;
    if (i < N_GRAPHS * NHID) g_pool[i] = 0.f;
}

__global__ void pool_kernel(const float* __restrict__ h,
                            const void* __restrict__ batch_raw) {
    int t = blockIdx.x * blockDim.x + threadIdx.x;
    int n = t >> 5;
    int c = (t & 31) << 2;
    int g = load_idx(batch_raw, n, g_idx64);
    float4 v = *(const float4*)(h + (size_t)n * NHID + c);
    red_add_v4(g_pool + g * NHID + c, v);
}

__global__ void lsm_kernel(float* __restrict__ out) {
    int r = blockIdx.x;
    int c = threadIdx.x;
    int w = c >> 5, lane = c & 31;
    __shared__ float smax[4], ssum[4];

    float v = g_pool[r * NHID + c];

    float m = v;
#pragma unroll
    for (int off = 16; off > 0; off >>= 1)
        m = fmaxf(m, __shfl_xor_sync(0xffffffffu, m, off));
    if (lane == 0) smax[w] = m;
    __syncthreads();
    m = fmaxf(fmaxf(smax[0], smax[1]), fmaxf(smax[2], smax[3]));

    float e = expf(v - m);
    float s = e;
#pragma unroll
    for (int off = 16; off > 0; off >>= 1)
        s += __shfl_xor_sync(0xffffffffu, s, off);
    if (lane == 0) ssum[w] = s;
    __syncthreads();
    s = ssum[0] + ssum[1] + ssum[2] + ssum[3];

    out[r * NHID + c] = (v - m) - logf(s);
}

// ---------------- launch -----------------------------------------------------
extern "C" void kernel_launch(void* const* d_in, const int* in_sizes, int n_in,
                              void* d_out, int out_size) {
    const float* x     = nullptr;
    const void*  ei    = nullptr;
    const void*  batch = nullptr;
    const float *W1 = nullptr, *b1 = nullptr, *W2 = nullptr, *b2 = nullptr;

    for (int i = 0; i < n_in; i++) {
        int sz = in_sizes[i];
        if (sz == N_NODES * NHID)            x = (const float*)d_in[i];
        else if (sz == 2 * N_EDGES)          ei = d_in[i];
        else if (sz == N_NODES)              batch = d_in[i];
        else if (sz == NLAYER * NHID * NHID) { if (!W1) W1 = (const float*)d_in[i]; else W2 = (const float*)d_in[i]; }
        else if (sz == NLAYER * NHID)        { if (!b1) b1 = (const float*)d_in[i]; else b2 = (const float*)d_in[i]; }
    }
    float* out = (float*)d_out;

    float *zp = nullptr, *hp = nullptr;
    cudaGetSymbolAddress((void**)&zp, g_z);
    cudaGetSymbolAddress((void**)&hp, g_h);

    cudaFuncSetAttribute(mlp_kernel, cudaFuncAttributeMaxDynamicSharedMemorySize, MLP_SMEM_BYTES);

    const int scan_blocks = (N_NODES + 1023) / 1024;        // 98
    const int edge_blocks = (N_EDGES + 255) / 256;          // 6250
    const int node_blocks = (N_NODES + 255) / 256;          // 391
    const int agg_blocks  = (N_NODES * 32 + 255) / 256;     // 12500
    const int mlp_blocks  = (N_NODES + 63) / 64;            // 1563
    const int pool_blocks = (N_NODES * 32) / 256;           // 12500

    // ---- CSR build (once per launch) ----
    detect_kernel<<<1, 32>>>((const int*)ei);
    deg_zero_kernel<<<node_blocks, 256>>>();
    hist_kernel<<<edge_blocks, 256>>>(ei);
    scan1_kernel<<<scan_blocks, 1024>>>();
    scan2_kernel<<<1, 128>>>(scan_blocks);
    scan3_kernel<<<node_blocks, 256>>>();
    fill_kernel<<<edge_blocks, 256>>>(ei);

    // ---- layers ----
    const float* hin = x;
    for (int l = 0; l < NLAYER; l++) {
        gin_agg_kernel<<<agg_blocks, 256>>>(hin, zp);
        mlp_kernel<<<mlp_blocks, 256, MLP_SMEM_BYTES>>>(
            zp, W1 + l * NHID * NHID, b1 + l * NHID,
            W2 + l * NHID * NHID, b2 + l * NHID, hp);
        hin = hp;
    }

    pool_zero_kernel<<<(N_GRAPHS * NHID + 255) / 256, 256>>>();
    pool_kernel<<<pool_blocks, 256>>>(hp, batch);
    lsm_kernel<<<N_GRAPHS, NHID>>>(out);
}

// round 9
// speedup vs baseline: 1.8973x; 1.2821x over previous
#include <cuda_runtime.h>
#include <cuda_bf16.h>
#include <cstdint>

#define N_NODES 100000
#define N_EDGES 1600000
#define N_GRAPHS 512
#define NHID 128
#define NLAYER 3

typedef unsigned long long ull;

// ---------------- scratch (static device arrays; no allocation) -------------
__device__ __align__(16) float g_z[(size_t)N_NODES * NHID];   // z = h + agg
__device__ __align__(16) float g_h[(size_t)N_NODES * NHID];   // layer out
__device__ __align__(16) float g_pool[N_GRAPHS * NHID];
__device__ int g_idx64;
__device__ int g_deg[N_NODES];
__device__ int g_rowoff[N_NODES + 1];
__device__ int g_csr_src[N_EDGES];
__device__ int g_bsum[128];
// bf16 weights, plain row-major [layer][mat][part(hi,lo)][128*128]
__device__ __align__(16) unsigned short g_wb[12 * 16384];

// ---------------- generic helpers -------------------------------------------
__device__ __forceinline__ void red_add_v4(float* addr, float4 v) {
    asm volatile("red.global.add.v4.f32 [%0], {%1,%2,%3,%4};"
                 :: "l"(addr), "f"(v.x), "f"(v.y), "f"(v.z), "f"(v.w)
                 : "memory");
}
__device__ __forceinline__ int load_idx(const void* raw, int i, int idx64) {
    return idx64 ? (int)((const long long*)raw)[i] : ((const int*)raw)[i];
}
__device__ __forceinline__ uint32_t smem_u32(const void* p) {
    uint32_t a;
    asm("{ .reg .u64 t; cvta.to.shared.u64 t, %1; cvt.u32.u64 %0, t; }"
        : "=r"(a) : "l"(p));
    return a;
}
__device__ __forceinline__ unsigned pack_bf16(__nv_bfloat16 a, __nv_bfloat16 b) {
    return (unsigned)__bfloat16_as_ushort(a) | ((unsigned)__bfloat16_as_ushort(b) << 16);
}

// ---------------- mma.sync helpers (sm_80+ portable) -------------------------
__device__ __forceinline__ void ldm_x4(uint32_t r[4], uint32_t addr) {
    asm volatile("ldmatrix.sync.aligned.m8n8.x4.shared.b16 {%0,%1,%2,%3}, [%4];"
                 : "=r"(r[0]), "=r"(r[1]), "=r"(r[2]), "=r"(r[3]) : "r"(addr));
}
__device__ __forceinline__ void ldm_x2(uint32_t r[2], uint32_t addr) {
    asm volatile("ldmatrix.sync.aligned.m8n8.x2.shared.b16 {%0,%1}, [%2];"
                 : "=r"(r[0]), "=r"(r[1]) : "r"(addr));
}
__device__ __forceinline__ void mma_bf16(float acc[4], const uint32_t a[4], const uint32_t b[2]) {
    asm volatile("mma.sync.aligned.m16n8k16.row.col.f32.bf16.bf16.f32 "
                 "{%0,%1,%2,%3}, {%4,%5,%6,%7}, {%8,%9}, {%0,%1,%2,%3};"
                 : "+f"(acc[0]), "+f"(acc[1]), "+f"(acc[2]), "+f"(acc[3])
                 : "r"(a[0]), "r"(a[1]), "r"(a[2]), "r"(a[3]),
                   "r"(b[0]), "r"(b[1]));
}

// ---------------- index-width detection --------------------------------------
__global__ void detect_kernel(const int* __restrict__ ei_raw) {
    if (threadIdx.x == 0) {
        int odd = 0;
        for (int i = 0; i < 64; i++) odd |= ei_raw[2 * i + 1];
        g_idx64 = (odd == 0) ? 1 : 0;
    }
}

// ---------------- CSR build ---------------------------------------------------
__global__ void deg_zero_kernel() {
    int i = blockIdx.x * blockDim.x + threadIdx.x;
    if (i < N_NODES) g_deg[i] = 0;
}
__global__ void hist_kernel(const void* __restrict__ ei_raw) {
    int e = blockIdx.x * blockDim.x + threadIdx.x;
    if (e < N_EDGES) atomicAdd(&g_deg[load_idx(ei_raw, N_EDGES + e, g_idx64)], 1);
}
__global__ void scan1_kernel() {
    __shared__ int wsum[32];
    int b = blockIdx.x, t = threadIdx.x;
    int gi = b * 1024 + t;
    int v = (gi < N_NODES) ? g_deg[gi] : 0;
    int lane = t & 31, w = t >> 5;
    int s = v;
#pragma unroll
    for (int o = 1; o < 32; o <<= 1) {
        int u = __shfl_up_sync(0xffffffffu, s, o);
        if (lane >= o) s += u;
    }
    if (lane == 31) wsum[w] = s;
    __syncthreads();
    if (w == 0) {
        int ws = wsum[lane];
#pragma unroll
        for (int o = 1; o < 32; o <<= 1) {
            int u = __shfl_up_sync(0xffffffffu, ws, o);
            if (lane >= o) ws += u;
        }
        wsum[lane] = ws;
    }
    __syncthreads();
    int excl = s - v + (w > 0 ? wsum[w - 1] : 0);
    if (gi < N_NODES) g_rowoff[gi] = excl;
    if (t == 1023) g_bsum[b] = excl + v;
}
__global__ void scan2_kernel(int nblocks) {
    if (threadIdx.x == 0) {
        int acc = 0;
        for (int i = 0; i < nblocks; i++) { int t = g_bsum[i]; g_bsum[i] = acc; acc += t; }
        g_rowoff[N_NODES] = N_EDGES;
    }
}
__global__ void scan3_kernel() {
    int i = blockIdx.x * blockDim.x + threadIdx.x;
    if (i < N_NODES) { g_rowoff[i] += g_bsum[i >> 10]; g_deg[i] = 0; }
}
__global__ void fill_kernel(const void* __restrict__ ei_raw) {
    int e = blockIdx.x * blockDim.x + threadIdx.x;
    if (e < N_EDGES) {
        int idx64 = g_idx64;
        int s = load_idx(ei_raw, e, idx64);
        int d = load_idx(ei_raw, N_EDGES + e, idx64);
        g_csr_src[g_rowoff[d] + atomicAdd(&g_deg[d], 1)] = s;
    }
}

// ---------------- aggregation: z = h + sum_{src in N(dst)} h[src] ------------
__global__ __launch_bounds__(256, 8)
void gin_agg_kernel(const float* __restrict__ h, float* __restrict__ z) {
    int gw = (blockIdx.x * blockDim.x + threadIdx.x) >> 5;
    if (gw >= N_NODES) return;
    int lane = threadIdx.x & 31;
    int c = lane << 2;
    float4 acc = *(const float4*)(h + (size_t)gw * NHID + c);
    int beg = g_rowoff[gw], end = g_rowoff[gw + 1];
    for (int i = beg; i < end; i += 32) {
        int cnt = min(32, end - i);
        int s = (lane < cnt) ? g_csr_src[i + lane] : 0;
        for (int j = 0; j < cnt; j++) {
            int sj = __shfl_sync(0xffffffffu, s, j);
            float4 v = *(const float4*)(h + (size_t)sj * NHID + c);
            acc.x += v.x; acc.y += v.y; acc.z += v.z; acc.w += v.w;
        }
    }
    *(float4*)(z + (size_t)gw * NHID + c) = acc;
}

// ---------------- weight conversion (fp32 -> plain bf16 hi/lo) ---------------
__global__ void wconv_kernel(const float* __restrict__ W1, const float* __restrict__ W2) {
    int l = blockIdx.x >> 1, m = blockIdx.x & 1;
    const float* W = (m == 0 ? W1 : W2) + l * NHID * NHID;
    unsigned short* hi = g_wb + (size_t)((l * 2 + m) * 2 + 0) * 16384;
    unsigned short* lo = g_wb + (size_t)((l * 2 + m) * 2 + 1) * 16384;
    for (int i = threadIdx.x + blockIdx.y * blockDim.x; i < 16384; i += blockDim.x) {
        float v = W[i];
        __nv_bfloat16 h = __float2bfloat16_rn(v);
        __nv_bfloat16 lw = __float2bfloat16_rn(v - __bfloat162float(h));
        hi[i] = __bfloat16_as_ushort(h);
        lo[i] = __bfloat16_as_ushort(lw);
    }
}

// ---------------- HMMA fused MLP ---------------------------------------------
// per CTA: 128 rows, full 2-layer MLP. bf16 hi/lo split (3 mma chains).
// smem tiles padded to 136 bf16/row (272 B = 17 x 16B chunks -> ldmatrix
// conflict-free). All 4 weight tiles staged once.
#define TROW 272                      // bytes per smem tile row
#define TILE_B (128 * TROW)           // 34816
#define SM_AHI  0
#define SM_ALO  TILE_B
#define SM_W1HI (2 * TILE_B)
#define SM_W1LO (3 * TILE_B)
#define SM_W2HI (4 * TILE_B)
#define SM_W2LO (5 * TILE_B)
#define SM_B1   (6 * TILE_B)
#define SM_B2   (6 * TILE_B + 512)
#define MMA_SMEM_BYTES (6 * TILE_B + 1024)   // 209920

__device__ __forceinline__ void gemm128(uint32_t sbase, uint32_t whi, uint32_t wlo,
                                        int wid, int lane, float acc[16][4]) {
    const uint32_t aaddr0 = sbase + ((wid << 4) + (lane & 15)) * TROW + ((lane >> 4) << 4);
    const uint32_t baddr0 = ((lane & 7)) * TROW + (((lane >> 3) & 1) << 4);
#pragma unroll
    for (int kk = 0; kk < 8; kk++) {
        uint32_t ka = kk * 32;
        uint32_t ahi[4], alo[4];
        ldm_x4(ahi, aaddr0 + SM_AHI + ka);
        ldm_x4(alo, aaddr0 + SM_ALO + ka);
#pragma unroll
        for (int nt = 0; nt < 16; nt++) {
            uint32_t wh[2], wl[2];
            uint32_t ba = sbase + baddr0 + (uint32_t)(nt * 8) * TROW + ka;
            ldm_x2(wh, ba + whi);
            ldm_x2(wl, ba + wlo);
            mma_bf16(acc[nt], ahi, wh);
            mma_bf16(acc[nt], ahi, wl);
            mma_bf16(acc[nt], alo, wh);
        }
    }
}

__global__ __launch_bounds__(256, 1)
void mlp_mma_kernel(const float* __restrict__ zin,
                    const unsigned short* __restrict__ wb,   // 4 tiles: w1hi,w1lo,w2hi,w2lo
                    const float* __restrict__ b1, const float* __restrict__ b2,
                    float* __restrict__ hout) {
    extern __shared__ char smem[];
    const uint32_t sbase = smem_u32(smem);
    const int tid = threadIdx.x;
    const int wid = tid >> 5;
    const int lane = tid & 31;
    const int row0 = blockIdx.x * 128;
    float* b1s = (float*)(smem + SM_B1);
    float* b2s = (float*)(smem + SM_B2);

    // stage 4 weight tiles (pad 128->136 bf16 rows)
#pragma unroll
    for (int t = 0; t < 4; t++) {
        const uint4* src = (const uint4*)(wb + (size_t)t * 16384);
        char* dst = smem + SM_W1HI + t * TILE_B;
        for (int i = tid; i < 2048; i += 256) {
            int r = i >> 4, c8 = i & 15;
            *(uint4*)(dst + r * TROW + c8 * 16) = src[i];
        }
    }
    if (tid < 128) { b1s[tid] = b1[tid]; b2s[tid] = b2[tid]; }

    // stage z -> A hi/lo
    for (int i = tid; i < 4096; i += 256) {   // 128 rows x 32 float4
        int r = i >> 5, c4 = i & 31;
        float4 v = make_float4(0.f, 0.f, 0.f, 0.f);
        if (row0 + r < N_NODES)
            v = *(const float4*)(zin + (size_t)(row0 + r) * NHID + c4 * 4);
        __nv_bfloat16 h0 = __float2bfloat16_rn(v.x), h1 = __float2bfloat16_rn(v.y);
        __nv_bfloat16 h2 = __float2bfloat16_rn(v.z), h3 = __float2bfloat16_rn(v.w);
        uint2 hv = make_uint2(pack_bf16(h0, h1), pack_bf16(h2, h3));
        uint2 lv = make_uint2(
            pack_bf16(__float2bfloat16_rn(v.x - __bfloat162float(h0)),
                      __float2bfloat16_rn(v.y - __bfloat162float(h1))),
            pack_bf16(__float2bfloat16_rn(v.z - __bfloat162float(h2)),
                      __float2bfloat16_rn(v.w - __bfloat162float(h3))));
        *(uint2*)(smem + SM_AHI + r * TROW + c4 * 8) = hv;
        *(uint2*)(smem + SM_ALO + r * TROW + c4 * 8) = lv;
    }
    __syncthreads();

    float acc[16][4];
    const int cpair = 2 * (lane & 3);
    const int rA = wid * 16 + (lane >> 2);   // row of c0/c1; rB = rA + 8

    // ---- GEMM1: t = relu(z @ W1^T + b1) ----
#pragma unroll
    for (int nt = 0; nt < 16; nt++) {
        float bb0 = b1s[nt * 8 + cpair], bb1 = b1s[nt * 8 + cpair + 1];
        acc[nt][0] = bb0; acc[nt][1] = bb1; acc[nt][2] = bb0; acc[nt][3] = bb1;
    }
    gemm128(sbase, SM_W1HI, SM_W1LO, wid, lane, acc);

    __syncthreads();   // all warps done reading A tiles

    // epilogue1: relu + hi/lo re-split into A tiles
#pragma unroll
    for (int nt = 0; nt < 16; nt++) {
        int col = nt * 8 + cpair;
        float v0 = fmaxf(acc[nt][0], 0.f), v1 = fmaxf(acc[nt][1], 0.f);
        float v2 = fmaxf(acc[nt][2], 0.f), v3 = fmaxf(acc[nt][3], 0.f);
        __nv_bfloat16 h0 = __float2bfloat16_rn(v0), h1 = __float2bfloat16_rn(v1);
        __nv_bfloat16 h2 = __float2bfloat16_rn(v2), h3 = __float2bfloat16_rn(v3);
        *(unsigned*)(smem + SM_AHI + rA * TROW + col * 2) = pack_bf16(h0, h1);
        *(unsigned*)(smem + SM_AHI + (rA + 8) * TROW + col * 2) = pack_bf16(h2, h3);
        *(unsigned*)(smem + SM_ALO + rA * TROW + col * 2) =
            pack_bf16(__float2bfloat16_rn(v0 - __bfloat162float(h0)),
                      __float2bfloat16_rn(v1 - __bfloat162float(h1)));
        *(unsigned*)(smem + SM_ALO + (rA + 8) * TROW + col * 2) =
            pack_bf16(__float2bfloat16_rn(v2 - __bfloat162float(h2)),
                      __float2bfloat16_rn(v3 - __bfloat162float(h3)));
    }
    __syncthreads();

    // ---- GEMM2: out = relu(t @ W2^T + b2) ----
#pragma unroll
    for (int nt = 0; nt < 16; nt++) {
        float bb0 = b2s[nt * 8 + cpair], bb1 = b2s[nt * 8 + cpair + 1];
        acc[nt][0] = bb0; acc[nt][1] = bb1; acc[nt][2] = bb0; acc[nt][3] = bb1;
    }
    gemm128(sbase, SM_W2HI, SM_W2LO, wid, lane, acc);

    // epilogue2: relu + store (float2 pairs, full 32B sectors)
    int grA = row0 + rA, grB = grA + 8;
#pragma unroll
    for (int nt = 0; nt < 16; nt++) {
        int col = nt * 8 + cpair;
        if (grA < N_NODES)
            *(float2*)(hout + (size_t)grA * NHID + col) =
                make_float2(fmaxf(acc[nt][0], 0.f), fmaxf(acc[nt][1], 0.f));
        if (grB < N_NODES)
            *(float2*)(hout + (size_t)grB * NHID + col) =
                make_float2(fmaxf(acc[nt][2], 0.f), fmaxf(acc[nt][3], 0.f));
    }
}

// ---------------- pooling + log_softmax --------------------------------------
__global__ void pool_zero_kernel() {
    int i = blockIdx.x * blockDim.x + threadIdx.x;
    if (i < N_GRAPHS * NHID) g_pool[i] = 0.f;
}
__global__ void pool_kernel(const float* __restrict__ h,
                            const void* __restrict__ batch_raw) {
    int t = blockIdx.x * blockDim.x + threadIdx.x;
    int n = t >> 5;
    int c = (t & 31) << 2;
    int g = load_idx(batch_raw, n, g_idx64);
    float4 v = *(const float4*)(h + (size_t)n * NHID + c);
    red_add_v4(g_pool + g * NHID + c, v);
}
__global__ void lsm_kernel(float* __restrict__ out) {
    int r = blockIdx.x;
    int c = threadIdx.x;
    int w = c >> 5, lane = c & 31;
    __shared__ float smax[4], ssum[4];
    float v = g_pool[r * NHID + c];
    float m = v;
#pragma unroll
    for (int off = 16; off > 0; off >>= 1)
        m = fmaxf(m, __shfl_xor_sync(0xffffffffu, m, off));
    if (lane == 0) smax[w] = m;
    __syncthreads();
    m = fmaxf(fmaxf(smax[0], smax[1]), fmaxf(smax[2], smax[3]));
    float e = expf(v - m);
    float s = e;
#pragma unroll
    for (int off = 16; off > 0; off >>= 1)
        s += __shfl_xor_sync(0xffffffffu, s, off);
    if (lane == 0) ssum[w] = s;
    __syncthreads();
    s = ssum[0] + ssum[1] + ssum[2] + ssum[3];
    out[r * NHID + c] = (v - m) - logf(s);
}

// ---------------- launch -----------------------------------------------------
extern "C" void kernel_launch(void* const* d_in, const int* in_sizes, int n_in,
                              void* d_out, int out_size) {
    const float* x     = nullptr;
    const void*  ei    = nullptr;
    const void*  batch = nullptr;
    const float *W1 = nullptr, *b1 = nullptr, *W2 = nullptr, *b2 = nullptr;
    for (int i = 0; i < n_in; i++) {
        int sz = in_sizes[i];
        if (sz == N_NODES * NHID)            x = (const float*)d_in[i];
        else if (sz == 2 * N_EDGES)          ei = d_in[i];
        else if (sz == N_NODES)              batch = d_in[i];
        else if (sz == NLAYER * NHID * NHID) { if (!W1) W1 = (const float*)d_in[i]; else W2 = (const float*)d_in[i]; }
        else if (sz == NLAYER * NHID)        { if (!b1) b1 = (const float*)d_in[i]; else b2 = (const float*)d_in[i]; }
    }
    float* out = (float*)d_out;

    float *zp = nullptr, *hp = nullptr;
    unsigned short* wb = nullptr;
    cudaGetSymbolAddress((void**)&zp, g_z);
    cudaGetSymbolAddress((void**)&hp, g_h);
    cudaGetSymbolAddress((void**)&wb, g_wb);

    cudaFuncSetAttribute(mlp_mma_kernel, cudaFuncAttributeMaxDynamicSharedMemorySize, MMA_SMEM_BYTES);

    const int scan_blocks = (N_NODES + 1023) / 1024;
    const int edge_blocks = (N_EDGES + 255) / 256;
    const int node_blocks = (N_NODES + 255) / 256;
    const int agg_blocks  = (N_NODES * 32 + 255) / 256;
    const int mlp_blocks  = (N_NODES + 127) / 128;   // 782
    const int pool_blocks = (N_NODES * 32) / 256;

    detect_kernel<<<1, 32>>>((const int*)ei);
    deg_zero_kernel<<<node_blocks, 256>>>();
    hist_kernel<<<edge_blocks, 256>>>(ei);
    scan1_kernel<<<scan_blocks, 1024>>>();
    scan2_kernel<<<1, 128>>>(scan_blocks);
    scan3_kernel<<<node_blocks, 256>>>();
    fill_kernel<<<edge_blocks, 256>>>(ei);
    wconv_kernel<<<dim3(6, 1), 256>>>(W1, W2);

    const float* hin = x;
    for (int l = 0; l < NLAYER; l++) {
        gin_agg_kernel<<<agg_blocks, 256>>>(hin, zp);
        mlp_mma_kernel<<<mlp_blocks, 256, MMA_SMEM_BYTES>>>(
            zp, wb + (size_t)l * 4 * 16384, b1 + l * NHID, b2 + l * NHID, hp);
        hin = hp;
    }

    pool_zero_kernel<<<(N_GRAPHS * NHID + 255) / 256, 256>>>();
    pool_kernel<<<pool_blocks, 256>>>(hp, batch);
    lsm_kernel<<<N_GRAPHS, NHID>>>(out);
}

// round 10
// speedup vs baseline: 1.9171x; 1.0104x over previous
#include <cuda_runtime.h>
#include <cuda_bf16.h>
#include <cstdint>

#define N_NODES 100000
#define N_EDGES 1600000
#define N_GRAPHS 512
#define NHID 128
#define NLAYER 3

typedef unsigned long long ull;

// ---------------- scratch (static device arrays; no allocation) -------------
__device__ __align__(16) float g_z[(size_t)N_NODES * NHID];   // z = h + agg
__device__ __align__(16) float g_h[(size_t)N_NODES * NHID];   // layer out
__device__ __align__(16) float g_pool[N_GRAPHS * NHID];
__device__ int g_idx64;
__device__ int g_deg[N_NODES];
__device__ int g_rowoff[N_NODES + 1];
__device__ int g_csr_src[N_EDGES];
__device__ int g_bsum[128];
// bf16 weights, plain row-major [layer][mat][part(hi,lo)][128*128]
__device__ __align__(16) unsigned short g_wb[12 * 16384];

// ---------------- generic helpers -------------------------------------------
__device__ __forceinline__ void red_add_v4(float* addr, float4 v) {
    asm volatile("red.global.add.v4.f32 [%0], {%1,%2,%3,%4};"
                 :: "l"(addr), "f"(v.x), "f"(v.y), "f"(v.z), "f"(v.w)
                 : "memory");
}
__device__ __forceinline__ int load_idx(const void* raw, int i, int idx64) {
    return idx64 ? (int)((const long long*)raw)[i] : ((const int*)raw)[i];
}
__device__ __forceinline__ uint32_t smem_u32(const void* p) {
    uint32_t a;
    asm("{ .reg .u64 t; cvta.to.shared.u64 t, %1; cvt.u32.u64 %0, t; }"
        : "=r"(a) : "l"(p));
    return a;
}
__device__ __forceinline__ unsigned pack_bf16(__nv_bfloat16 a, __nv_bfloat16 b) {
    return (unsigned)__bfloat16_as_ushort(a) | ((unsigned)__bfloat16_as_ushort(b) << 16);
}

// ---------------- mma.sync helpers (sm_80+ portable) -------------------------
__device__ __forceinline__ void ldm_x4(uint32_t r[4], uint32_t addr) {
    asm volatile("ldmatrix.sync.aligned.m8n8.x4.shared.b16 {%0,%1,%2,%3}, [%4];"
                 : "=r"(r[0]), "=r"(r[1]), "=r"(r[2]), "=r"(r[3]) : "r"(addr));
}
__device__ __forceinline__ void mma_bf16(float acc[4], const uint32_t a[4], const uint32_t b[2]) {
    asm volatile("mma.sync.aligned.m16n8k16.row.col.f32.bf16.bf16.f32 "
                 "{%0,%1,%2,%3}, {%4,%5,%6,%7}, {%8,%9}, {%0,%1,%2,%3};"
                 : "+f"(acc[0]), "+f"(acc[1]), "+f"(acc[2]), "+f"(acc[3])
                 : "r"(a[0]), "r"(a[1]), "r"(a[2]), "r"(a[3]),
                   "r"(b[0]), "r"(b[1]));
}

// ---------------- index-width detection --------------------------------------
__global__ void detect_kernel(const int* __restrict__ ei_raw) {
    if (threadIdx.x == 0) {
        int odd = 0;
        for (int i = 0; i < 64; i++) odd |= ei_raw[2 * i + 1];
        g_idx64 = (odd == 0) ? 1 : 0;
    }
}

// ---------------- CSR build ---------------------------------------------------
__global__ void deg_zero_kernel() {
    int i = blockIdx.x * blockDim.x + threadIdx.x;
    if (i < N_NODES) g_deg[i] = 0;
}
__global__ void hist_kernel(const void* __restrict__ ei_raw) {
    int e = blockIdx.x * blockDim.x + threadIdx.x;
    if (e < N_EDGES) atomicAdd(&g_deg[load_idx(ei_raw, N_EDGES + e, g_idx64)], 1);
}
__global__ void scan1_kernel() {
    __shared__ int wsum[32];
    int b = blockIdx.x, t = threadIdx.x;
    int gi = b * 1024 + t;
    int v = (gi < N_NODES) ? g_deg[gi] : 0;
    int lane = t & 31, w = t >> 5;
    int s = v;
#pragma unroll
    for (int o = 1; o < 32; o <<= 1) {
        int u = __shfl_up_sync(0xffffffffu, s, o);
        if (lane >= o) s += u;
    }
    if (lane == 31) wsum[w] = s;
    __syncthreads();
    if (w == 0) {
        int ws = wsum[lane];
#pragma unroll
        for (int o = 1; o < 32; o <<= 1) {
            int u = __shfl_up_sync(0xffffffffu, ws, o);
            if (lane >= o) ws += u;
        }
        wsum[lane] = ws;
    }
    __syncthreads();
    int excl = s - v + (w > 0 ? wsum[w - 1] : 0);
    if (gi < N_NODES) g_rowoff[gi] = excl;
    if (t == 1023) g_bsum[b] = excl + v;
}
__global__ void scan2_kernel(int nblocks) {
    if (threadIdx.x == 0) {
        int acc = 0;
        for (int i = 0; i < nblocks; i++) { int t = g_bsum[i]; g_bsum[i] = acc; acc += t; }
        g_rowoff[N_NODES] = N_EDGES;
    }
}
__global__ void scan3_kernel() {
    int i = blockIdx.x * blockDim.x + threadIdx.x;
    if (i < N_NODES) { g_rowoff[i] += g_bsum[i >> 10]; g_deg[i] = 0; }
}
__global__ void fill_kernel(const void* __restrict__ ei_raw) {
    int e = blockIdx.x * blockDim.x + threadIdx.x;
    if (e < N_EDGES) {
        int idx64 = g_idx64;
        int s = load_idx(ei_raw, e, idx64);
        int d = load_idx(ei_raw, N_EDGES + e, idx64);
        g_csr_src[g_rowoff[d] + atomicAdd(&g_deg[d], 1)] = s;
    }
}

// ---------------- aggregation: z = h + sum_{src in N(dst)} h[src] ------------
__global__ __launch_bounds__(256, 8)
void gin_agg_kernel(const float* __restrict__ h, float* __restrict__ z) {
    int gw = (blockIdx.x * blockDim.x + threadIdx.x) >> 5;
    if (gw >= N_NODES) return;
    int lane = threadIdx.x & 31;
    int c = lane << 2;
    float4 acc = *(const float4*)(h + (size_t)gw * NHID + c);
    int beg = g_rowoff[gw], end = g_rowoff[gw + 1];
    for (int i = beg; i < end; i += 32) {
        int cnt = min(32, end - i);
        int s = (lane < cnt) ? g_csr_src[i + lane] : 0;
        for (int j = 0; j < cnt; j++) {
            int sj = __shfl_sync(0xffffffffu, s, j);
            float4 v = *(const float4*)(h + (size_t)sj * NHID + c);
            acc.x += v.x; acc.y += v.y; acc.z += v.z; acc.w += v.w;
        }
    }
    *(float4*)(z + (size_t)gw * NHID + c) = acc;
}

// ---------------- weight conversion (fp32 -> plain bf16 hi/lo) ---------------
__global__ void wconv_kernel(const float* __restrict__ W1, const float* __restrict__ W2) {
    int l = blockIdx.x >> 1, m = blockIdx.x & 1;
    const float* W = (m == 0 ? W1 : W2) + l * NHID * NHID;
    unsigned short* hi = g_wb + (size_t)((l * 2 + m) * 2 + 0) * 16384;
    unsigned short* lo = g_wb + (size_t)((l * 2 + m) * 2 + 1) * 16384;
    for (int i = threadIdx.x; i < 16384; i += blockDim.x) {
        float v = W[i];
        __nv_bfloat16 h = __float2bfloat16_rn(v);
        __nv_bfloat16 lw = __float2bfloat16_rn(v - __bfloat162float(h));
        hi[i] = __bfloat16_as_ushort(h);
        lo[i] = __bfloat16_as_ushort(lw);
    }
}

// ---------------- HMMA fused MLP ---------------------------------------------
// per CTA: 128 rows, full 2-layer MLP. bf16 hi/lo split (3 mma chains).
// Warp tile: 32 rows x 64 cols (8 warps = 4 M-groups x 2 N-groups).
// W fragments loaded with ldmatrix.x4 covering 2 n-tiles x 2 k-halves.
// smem tiles padded to 136 bf16/row (272 B -> ldmatrix conflict-free).
#define TROW 272
#define TILE_B (128 * TROW)           // 34816
#define SM_AHI  0
#define SM_ALO  TILE_B
#define SM_W1HI (2 * TILE_B)
#define SM_W1LO (3 * TILE_B)
#define SM_W2HI (4 * TILE_B)
#define SM_W2LO (5 * TILE_B)
#define SM_B1   (6 * TILE_B)
#define SM_B2   (6 * TILE_B + 512)
#define MMA_SMEM_BYTES (6 * TILE_B + 1024)   // 209920

__device__ __forceinline__ void gemm128(uint32_t sbase, uint32_t whi, uint32_t wlo,
                                        int wid, int lane, float acc[2][8][4]) {
    const int mg = wid >> 1;   // 0..3 -> rows mg*32..mg*32+31
    const int ng = wid & 1;    // 0..1 -> cols ng*64..ng*64+63
    // A x4: lanes 0-15 -> 16 rows k0-half; lanes 16-31 -> same rows +16B (k8)
    const uint32_t a0 = sbase + (uint32_t)(mg * 32 + (lane & 15)) * TROW
                      + (((uint32_t)lane >> 4) << 4);
    // W x4: lanes 0-7 nt rows k0 / 8-15 nt rows k8 / 16-23 nt+1 rows k0 / 24-31 nt+1 k8
    const uint32_t wb0 = (uint32_t)(ng * 64 + ((lane >> 4) & 1) * 8 + (lane & 7)) * TROW
                       + ((((uint32_t)lane >> 3) & 1) << 4);
#pragma unroll
    for (int kk = 0; kk < 8; kk++) {
        const uint32_t ka = kk * 32;
        uint32_t ahi0[4], alo0[4], ahi1[4], alo1[4];
        ldm_x4(ahi0, a0 + SM_AHI + ka);
        ldm_x4(alo0, a0 + SM_ALO + ka);
        ldm_x4(ahi1, a0 + 16 * TROW + SM_AHI + ka);
        ldm_x4(alo1, a0 + 16 * TROW + SM_ALO + ka);
#pragma unroll
        for (int p = 0; p < 4; p++) {
            uint32_t wh[4], wl[4];
            const uint32_t ba = sbase + wb0 + (uint32_t)(p * 16) * TROW + ka;
            ldm_x4(wh, ba + whi);
            ldm_x4(wl, ba + wlo);
            // nt = 2p -> frags wh[0..1]; nt = 2p+1 -> wh[2..3]
            mma_bf16(acc[0][2 * p],     ahi0, wh);
            mma_bf16(acc[0][2 * p],     ahi0, wl);
            mma_bf16(acc[0][2 * p],     alo0, wh);
            mma_bf16(acc[0][2 * p + 1], ahi0, wh + 2);
            mma_bf16(acc[0][2 * p + 1], ahi0, wl + 2);
            mma_bf16(acc[0][2 * p + 1], alo0, wh + 2);
            mma_bf16(acc[1][2 * p],     ahi1, wh);
            mma_bf16(acc[1][2 * p],     ahi1, wl);
            mma_bf16(acc[1][2 * p],     alo1, wh);
            mma_bf16(acc[1][2 * p + 1], ahi1, wh + 2);
            mma_bf16(acc[1][2 * p + 1], ahi1, wl + 2);
            mma_bf16(acc[1][2 * p + 1], alo1, wh + 2);
        }
    }
}

__global__ __launch_bounds__(256, 1)
void mlp_mma_kernel(const float* __restrict__ zin,
                    const unsigned short* __restrict__ wb,   // w1hi,w1lo,w2hi,w2lo
                    const float* __restrict__ b1, const float* __restrict__ b2,
                    float* __restrict__ hout) {
    extern __shared__ char smem[];
    const uint32_t sbase = smem_u32(smem);
    const int tid = threadIdx.x;
    const int wid = tid >> 5;
    const int lane = tid & 31;
    const int row0 = blockIdx.x * 128;
    float* b1s = (float*)(smem + SM_B1);
    float* b2s = (float*)(smem + SM_B2);

    // stage 4 weight tiles (pad 128->136 bf16 rows)
#pragma unroll
    for (int t = 0; t < 4; t++) {
        const uint4* src = (const uint4*)(wb + (size_t)t * 16384);
        char* dst = smem + SM_W1HI + t * TILE_B;
        for (int i = tid; i < 2048; i += 256) {
            int r = i >> 4, c8 = i & 15;
            *(uint4*)(dst + r * TROW + c8 * 16) = src[i];
        }
    }
    if (tid < 128) { b1s[tid] = b1[tid]; b2s[tid] = b2[tid]; }

    // stage z -> A hi/lo
    for (int i = tid; i < 4096; i += 256) {
        int r = i >> 5, c4 = i & 31;
        float4 v = make_float4(0.f, 0.f, 0.f, 0.f);
        if (row0 + r < N_NODES)
            v = *(const float4*)(zin + (size_t)(row0 + r) * NHID + c4 * 4);
        __nv_bfloat16 h0 = __float2bfloat16_rn(v.x), h1 = __float2bfloat16_rn(v.y);
        __nv_bfloat16 h2 = __float2bfloat16_rn(v.z), h3 = __float2bfloat16_rn(v.w);
        uint2 hv = make_uint2(pack_bf16(h0, h1), pack_bf16(h2, h3));
        uint2 lv = make_uint2(
            pack_bf16(__float2bfloat16_rn(v.x - __bfloat162float(h0)),
                      __float2bfloat16_rn(v.y - __bfloat162float(h1))),
            pack_bf16(__float2bfloat16_rn(v.z - __bfloat162float(h2)),
                      __float2bfloat16_rn(v.w - __bfloat162float(h3))));
        *(uint2*)(smem + SM_AHI + r * TROW + c4 * 8) = hv;
        *(uint2*)(smem + SM_ALO + r * TROW + c4 * 8) = lv;
    }
    __syncthreads();

    const int mg = wid >> 1, ng = wid & 1;
    const int cpair = 2 * (lane & 3);
    float acc[2][8][4];

    // ---- GEMM1: t = relu(z @ W1^T + b1) ----
#pragma unroll
    for (int m = 0; m < 2; m++)
#pragma unroll
        for (int nt = 0; nt < 8; nt++) {
            int col = ng * 64 + (nt >> 1) * 16 + (nt & 1) * 8 + cpair;
            float bb0 = b1s[col], bb1 = b1s[col + 1];
            acc[m][nt][0] = bb0; acc[m][nt][1] = bb1;
            acc[m][nt][2] = bb0; acc[m][nt][3] = bb1;
        }
    gemm128(sbase, SM_W1HI, SM_W1LO, wid, lane, acc);

    __syncthreads();   // all warps done reading A tiles

    // epilogue1: relu + hi/lo re-split into A tiles
#pragma unroll
    for (int m = 0; m < 2; m++) {
        int rA = mg * 32 + m * 16 + (lane >> 2);
#pragma unroll
        for (int nt = 0; nt < 8; nt++) {
            int col = ng * 64 + (nt >> 1) * 16 + (nt & 1) * 8 + cpair;
            float v0 = fmaxf(acc[m][nt][0], 0.f), v1 = fmaxf(acc[m][nt][1], 0.f);
            float v2 = fmaxf(acc[m][nt][2], 0.f), v3 = fmaxf(acc[m][nt][3], 0.f);
            __nv_bfloat16 h0 = __float2bfloat16_rn(v0), h1 = __float2bfloat16_rn(v1);
            __nv_bfloat16 h2 = __float2bfloat16_rn(v2), h3 = __float2bfloat16_rn(v3);
            *(unsigned*)(smem + SM_AHI + rA * TROW + col * 2) = pack_bf16(h0, h1);
            *(unsigned*)(smem + SM_AHI + (rA + 8) * TROW + col * 2) = pack_bf16(h2, h3);
            *(unsigned*)(smem + SM_ALO + rA * TROW + col * 2) =
                pack_bf16(__float2bfloat16_rn(v0 - __bfloat162float(h0)),
                          __float2bfloat16_rn(v1 - __bfloat162float(h1)));
            *(unsigned*)(smem + SM_ALO + (rA + 8) * TROW + col * 2) =
                pack_bf16(__float2bfloat16_rn(v2 - __bfloat162float(h2)),
                          __float2bfloat16_rn(v3 - __bfloat162float(h3)));
        }
    }
    __syncthreads();

    // ---- GEMM2: out = relu(t @ W2^T + b2) ----
#pragma unroll
    for (int m = 0; m < 2; m++)
#pragma unroll
        for (int nt = 0; nt < 8; nt++) {
            int col = ng * 64 + (nt >> 1) * 16 + (nt & 1) * 8 + cpair;
            float bb0 = b2s[col], bb1 = b2s[col + 1];
            acc[m][nt][0] = bb0; acc[m][nt][1] = bb1;
            acc[m][nt][2] = bb0; acc[m][nt][3] = bb1;
        }
    gemm128(sbase, SM_W2HI, SM_W2LO, wid, lane, acc);

    // epilogue2: relu + store (float2 pairs)
#pragma unroll
    for (int m = 0; m < 2; m++) {
        int grA = row0 + mg * 32 + m * 16 + (lane >> 2);
        int grB = grA + 8;
#pragma unroll
        for (int nt = 0; nt < 8; nt++) {
            int col = ng * 64 + (nt >> 1) * 16 + (nt & 1) * 8 + cpair;
            if (grA < N_NODES)
                *(float2*)(hout + (size_t)grA * NHID + col) =
                    make_float2(fmaxf(acc[m][nt][0], 0.f), fmaxf(acc[m][nt][1], 0.f));
            if (grB < N_NODES)
                *(float2*)(hout + (size_t)grB * NHID + col) =
                    make_float2(fmaxf(acc[m][nt][2], 0.f), fmaxf(acc[m][nt][3], 0.f));
        }
    }
}

// ---------------- pooling + log_softmax --------------------------------------
__global__ void pool_zero_kernel() {
    int i = blockIdx.x * blockDim.x + threadIdx.x;
    if (i < N_GRAPHS * NHID) g_pool[i] = 0.f;
}
__global__ void pool_kernel(const float* __restrict__ h,
                            const void* __restrict__ batch_raw) {
    int t = blockIdx.x * blockDim.x + threadIdx.x;
    int n = t >> 5;
    int c = (t & 31) << 2;
    int g = load_idx(batch_raw, n, g_idx64);
    float4 v = *(const float4*)(h + (size_t)n * NHID + c);
    red_add_v4(g_pool + g * NHID + c, v);
}
__global__ void lsm_kernel(float* __restrict__ out) {
    int r = blockIdx.x;
    int c = threadIdx.x;
    int w = c >> 5, lane = c & 31;
    __shared__ float smax[4], ssum[4];
    float v = g_pool[r * NHID + c];
    float m = v;
#pragma unroll
    for (int off = 16; off > 0; off >>= 1)
        m = fmaxf(m, __shfl_xor_sync(0xffffffffu, m, off));
    if (lane == 0) smax[w] = m;
    __syncthreads();
    m = fmaxf(fmaxf(smax[0], smax[1]), fmaxf(smax[2], smax[3]));
    float e = expf(v - m);
    float s = e;
#pragma unroll
    for (int off = 16; off > 0; off >>= 1)
        s += __shfl_xor_sync(0xffffffffu, s, off);
    if (lane == 0) ssum[w] = s;
    __syncthreads();
    s = ssum[0] + ssum[1] + ssum[2] + ssum[3];
    out[r * NHID + c] = (v - m) - logf(s);
}

// ---------------- launch -----------------------------------------------------
extern "C" void kernel_launch(void* const* d_in, const int* in_sizes, int n_in,
                              void* d_out, int out_size) {
    const float* x     = nullptr;
    const void*  ei    = nullptr;
    const void*  batch = nullptr;
    const float *W1 = nullptr, *b1 = nullptr, *W2 = nullptr, *b2 = nullptr;
    for (int i = 0; i < n_in; i++) {
        int sz = in_sizes[i];
        if (sz == N_NODES * NHID)            x = (const float*)d_in[i];
        else if (sz == 2 * N_EDGES)          ei = d_in[i];
        else if (sz == N_NODES)              batch = d_in[i];
        else if (sz == NLAYER * NHID * NHID) { if (!W1) W1 = (const float*)d_in[i]; else W2 = (const float*)d_in[i]; }
        else if (sz == NLAYER * NHID)        { if (!b1) b1 = (const float*)d_in[i]; else b2 = (const float*)d_in[i]; }
    }
    float* out = (float*)d_out;

    float *zp = nullptr, *hp = nullptr;
    unsigned short* wb = nullptr;
    cudaGetSymbolAddress((void**)&zp, g_z);
    cudaGetSymbolAddress((void**)&hp, g_h);
    cudaGetSymbolAddress((void**)&wb, g_wb);

    cudaFuncSetAttribute(mlp_mma_kernel, cudaFuncAttributeMaxDynamicSharedMemorySize, MMA_SMEM_BYTES);

    const int scan_blocks = (N_NODES + 1023) / 1024;
    const int edge_blocks = (N_EDGES + 255) / 256;
    const int node_blocks = (N_NODES + 255) / 256;
    const int agg_blocks  = (N_NODES * 32 + 255) / 256;
    const int mlp_blocks  = (N_NODES + 127) / 128;   // 782
    const int pool_blocks = (N_NODES * 32) / 256;

    detect_kernel<<<1, 32>>>((const int*)ei);
    deg_zero_kernel<<<node_blocks, 256>>>();
    hist_kernel<<<edge_blocks, 256>>>(ei);
    scan1_kernel<<<scan_blocks, 1024>>>();
    scan2_kernel<<<1, 128>>>(scan_blocks);
    scan3_kernel<<<node_blocks, 256>>>();
    fill_kernel<<<edge_blocks, 256>>>(ei);
    wconv_kernel<<<6, 256>>>(W1, W2);

    const float* hin = x;
    for (int l = 0; l < NLAYER; l++) {
        gin_agg_kernel<<<agg_blocks, 256>>>(hin, zp);
        mlp_mma_kernel<<<mlp_blocks, 256, MMA_SMEM_BYTES>>>(
            zp, wb + (size_t)l * 4 * 16384, b1 + l * NHID, b2 + l * NHID, hp);
        hin = hp;
    }

    pool_zero_kernel<<<(N_GRAPHS * NHID + 255) / 256, 256>>>();
    pool_kernel<<<pool_blocks, 256>>>(hp, batch);
    lsm_kernel<<<N_GRAPHS, NHID>>>(out);
}

// round 11
// speedup vs baseline: 2.0377x; 1.0629x over previous
#include <cuda_runtime.h>
#include <cuda_bf16.h>
#include <cstdint>

#define N_NODES 100000
#define N_EDGES 1600000
#define N_GRAPHS 512
#define NHID 128
#define NLAYER 3

typedef unsigned long long ull;

// ---------------- scratch (static device arrays; no allocation) -------------
__device__ __align__(16) float g_z[(size_t)N_NODES * NHID];   // z = h + agg
__device__ __align__(16) float g_h[(size_t)N_NODES * NHID];   // layer out
__device__ __align__(16) float g_pool[N_GRAPHS * NHID];
__device__ int g_idx64;
__device__ int g_deg[N_NODES];
__device__ int g_rowoff[N_NODES + 1];
__device__ int g_csr_src[N_EDGES];
__device__ int g_bsum[128];
// bf16 weights, plain row-major [layer][mat][part(hi,lo)][128*128]
__device__ __align__(16) unsigned short g_wb[12 * 16384];

// ---------------- generic helpers -------------------------------------------
__device__ __forceinline__ void red_add_v4(float* addr, float4 v) {
    asm volatile("red.global.add.v4.f32 [%0], {%1,%2,%3,%4};"
                 :: "l"(addr), "f"(v.x), "f"(v.y), "f"(v.z), "f"(v.w)
                 : "memory");
}
__device__ __forceinline__ int load_idx(const void* raw, int i, int idx64) {
    return idx64 ? (int)((const long long*)raw)[i] : ((const int*)raw)[i];
}
__device__ __forceinline__ uint32_t smem_u32(const void* p) {
    uint32_t a;
    asm("{ .reg .u64 t; cvta.to.shared.u64 t, %1; cvt.u32.u64 %0, t; }"
        : "=r"(a) : "l"(p));
    return a;
}
__device__ __forceinline__ unsigned pack_bf16(__nv_bfloat16 a, __nv_bfloat16 b) {
    return (unsigned)__bfloat16_as_ushort(a) | ((unsigned)__bfloat16_as_ushort(b) << 16);
}

// ---------------- mma.sync helpers (sm_80+ portable) -------------------------
__device__ __forceinline__ void ldm_x4(uint32_t r[4], uint32_t addr) {
    asm volatile("ldmatrix.sync.aligned.m8n8.x4.shared.b16 {%0,%1,%2,%3}, [%4];"
                 : "=r"(r[0]), "=r"(r[1]), "=r"(r[2]), "=r"(r[3]) : "r"(addr));
}
__device__ __forceinline__ void mma_bf16(float acc[4], const uint32_t a[4], const uint32_t b[2]) {
    asm volatile("mma.sync.aligned.m16n8k16.row.col.f32.bf16.bf16.f32 "
                 "{%0,%1,%2,%3}, {%4,%5,%6,%7}, {%8,%9}, {%0,%1,%2,%3};"
                 : "+f"(acc[0]), "+f"(acc[1]), "+f"(acc[2]), "+f"(acc[3])
                 : "r"(a[0]), "r"(a[1]), "r"(a[2]), "r"(a[3]),
                   "r"(b[0]), "r"(b[1]));
}

// ---------------- index-width detection --------------------------------------
__global__ void detect_kernel(const int* __restrict__ ei_raw) {
    if (threadIdx.x == 0) {
        int odd = 0;
        for (int i = 0; i < 64; i++) odd |= ei_raw[2 * i + 1];
        g_idx64 = (odd == 0) ? 1 : 0;
    }
}

// ---------------- CSR build ---------------------------------------------------
__global__ void deg_zero_kernel() {
    int i = blockIdx.x * blockDim.x + threadIdx.x;
    if (i < N_NODES) g_deg[i] = 0;
}
__global__ void hist_kernel(const void* __restrict__ ei_raw) {
    int e = blockIdx.x * blockDim.x + threadIdx.x;
    if (e < N_EDGES) atomicAdd(&g_deg[load_idx(ei_raw, N_EDGES + e, g_idx64)], 1);
}
__global__ void scan1_kernel() {
    __shared__ int wsum[32];
    int b = blockIdx.x, t = threadIdx.x;
    int gi = b * 1024 + t;
    int v = (gi < N_NODES) ? g_deg[gi] : 0;
    int lane = t & 31, w = t >> 5;
    int s = v;
#pragma unroll
    for (int o = 1; o < 32; o <<= 1) {
        int u = __shfl_up_sync(0xffffffffu, s, o);
        if (lane >= o) s += u;
    }
    if (lane == 31) wsum[w] = s;
    __syncthreads();
    if (w == 0) {
        int ws = wsum[lane];
#pragma unroll
        for (int o = 1; o < 32; o <<= 1) {
            int u = __shfl_up_sync(0xffffffffu, ws, o);
            if (lane >= o) ws += u;
        }
        wsum[lane] = ws;
    }
    __syncthreads();
    int excl = s - v + (w > 0 ? wsum[w - 1] : 0);
    if (gi < N_NODES) g_rowoff[gi] = excl;
    if (t == 1023) g_bsum[b] = excl + v;
}
__global__ void scan2_kernel(int nblocks) {
    if (threadIdx.x == 0) {
        int acc = 0;
        for (int i = 0; i < nblocks; i++) { int t = g_bsum[i]; g_bsum[i] = acc; acc += t; }
        g_rowoff[N_NODES] = N_EDGES;
    }
}
__global__ void scan3_kernel() {
    int i = blockIdx.x * blockDim.x + threadIdx.x;
    if (i < N_NODES) { g_rowoff[i] += g_bsum[i >> 10]; g_deg[i] = 0; }
}
__global__ void fill_kernel(const void* __restrict__ ei_raw) {
    int e = blockIdx.x * blockDim.x + threadIdx.x;
    if (e < N_EDGES) {
        int idx64 = g_idx64;
        int s = load_idx(ei_raw, e, idx64);
        int d = load_idx(ei_raw, N_EDGES + e, idx64);
        g_csr_src[g_rowoff[d] + atomicAdd(&g_deg[d], 1)] = s;
    }
}

// ---------------- aggregation: z = h + sum_{src in N(dst)} h[src] ------------
__global__ __launch_bounds__(256, 8)
void gin_agg_kernel(const float* __restrict__ h, float* __restrict__ z) {
    int gw = (blockIdx.x * blockDim.x + threadIdx.x) >> 5;
    if (gw >= N_NODES) return;
    int lane = threadIdx.x & 31;
    int c = lane << 2;
    float4 acc = *(const float4*)(h + (size_t)gw * NHID + c);
    int beg = g_rowoff[gw], end = g_rowoff[gw + 1];
    for (int i = beg; i < end; i += 32) {
        int cnt = min(32, end - i);
        int s = (lane < cnt) ? g_csr_src[i + lane] : 0;
        for (int j = 0; j < cnt; j++) {
            int sj = __shfl_sync(0xffffffffu, s, j);
            float4 v = *(const float4*)(h + (size_t)sj * NHID + c);
            acc.x += v.x; acc.y += v.y; acc.z += v.z; acc.w += v.w;
        }
    }
    *(float4*)(z + (size_t)gw * NHID + c) = acc;
}

// ---------------- weight conversion (fp32 -> plain bf16 hi/lo) ---------------
__global__ void wconv_kernel(const float* __restrict__ W1, const float* __restrict__ W2) {
    int l = blockIdx.x >> 1, m = blockIdx.x & 1;
    const float* W = (m == 0 ? W1 : W2) + l * NHID * NHID;
    unsigned short* hi = g_wb + (size_t)((l * 2 + m) * 2 + 0) * 16384;
    unsigned short* lo = g_wb + (size_t)((l * 2 + m) * 2 + 1) * 16384;
    for (int i = threadIdx.x; i < 16384; i += blockDim.x) {
        float v = W[i];
        __nv_bfloat16 h = __float2bfloat16_rn(v);
        __nv_bfloat16 lw = __float2bfloat16_rn(v - __bfloat162float(h));
        hi[i] = __bfloat16_as_ushort(h);
        lo[i] = __bfloat16_as_ushort(lw);
    }
}

// ---------------- HMMA fused MLP ---------------------------------------------
// per CTA: 128 rows, full 2-layer MLP. bf16 hi/lo split (3 mma chains).
// 512 threads = 16 warps (8 M-groups x 2 N-groups); warp tile 16 rows x 64 cols.
// W fragments loaded with ldmatrix.x4 covering 2 n-tiles x 2 k-halves.
// smem tiles padded to 136 bf16/row (272 B -> ldmatrix conflict-free).
#define TROW 272
#define TILE_B (128 * TROW)           // 34816
#define SM_AHI  0
#define SM_ALO  TILE_B
#define SM_W1HI (2 * TILE_B)
#define SM_W1LO (3 * TILE_B)
#define SM_W2HI (4 * TILE_B)
#define SM_W2LO (5 * TILE_B)
#define SM_B1   (6 * TILE_B)
#define SM_B2   (6 * TILE_B + 512)
#define MMA_SMEM_BYTES (6 * TILE_B + 1024)   // 209920
#define MLP_THREADS 512

__device__ __forceinline__ void gemm128(uint32_t sbase, uint32_t whi, uint32_t wlo,
                                        int wid, int lane, float acc[8][4]) {
    const int mg = wid >> 1;   // 0..7 -> rows mg*16..mg*16+15
    const int ng = wid & 1;    // 0..1 -> cols ng*64..ng*64+63
    // A x4: lanes 0-15 -> 16 rows k0-half; lanes 16-31 -> same rows +16B (k8)
    const uint32_t a0 = sbase + (uint32_t)(mg * 16 + (lane & 15)) * TROW
                      + (((uint32_t)lane >> 4) << 4);
    // W x4: lanes 0-7 nt rows k0 / 8-15 nt rows k8 / 16-23 nt+1 rows k0 / 24-31 nt+1 k8
    const uint32_t wb0 = (uint32_t)(ng * 64 + ((lane >> 4) & 1) * 8 + (lane & 7)) * TROW
                       + ((((uint32_t)lane >> 3) & 1) << 4);
#pragma unroll
    for (int kk = 0; kk < 8; kk++) {
        const uint32_t ka = kk * 32;
        uint32_t ahi[4], alo[4];
        ldm_x4(ahi, a0 + SM_AHI + ka);
        ldm_x4(alo, a0 + SM_ALO + ka);
#pragma unroll
        for (int p = 0; p < 4; p++) {
            uint32_t wh[4], wl[4];
            const uint32_t ba = sbase + wb0 + (uint32_t)(p * 16) * TROW + ka;
            ldm_x4(wh, ba + whi);
            ldm_x4(wl, ba + wlo);
            // nt = 2p -> frags wh[0..1]; nt = 2p+1 -> wh[2..3]
            mma_bf16(acc[2 * p],     ahi, wh);
            mma_bf16(acc[2 * p],     ahi, wl);
            mma_bf16(acc[2 * p],     alo, wh);
            mma_bf16(acc[2 * p + 1], ahi, wh + 2);
            mma_bf16(acc[2 * p + 1], ahi, wl + 2);
            mma_bf16(acc[2 * p + 1], alo, wh + 2);
        }
    }
}

__global__ __launch_bounds__(MLP_THREADS, 1)
void mlp_mma_kernel(const float* __restrict__ zin,
                    const unsigned short* __restrict__ wb,   // w1hi,w1lo,w2hi,w2lo
                    const float* __restrict__ b1, const float* __restrict__ b2,
                    float* __restrict__ hout) {
    extern __shared__ char smem[];
    const uint32_t sbase = smem_u32(smem);
    const int tid = threadIdx.x;
    const int wid = tid >> 5;
    const int lane = tid & 31;
    const int row0 = blockIdx.x * 128;
    float* b1s = (float*)(smem + SM_B1);
    float* b2s = (float*)(smem + SM_B2);

    // stage 4 weight tiles (pad 128->136 bf16 rows)
#pragma unroll
    for (int t = 0; t < 4; t++) {
        const uint4* src = (const uint4*)(wb + (size_t)t * 16384);
        char* dst = smem + SM_W1HI + t * TILE_B;
        for (int i = tid; i < 2048; i += MLP_THREADS) {
            int r = i >> 4, c8 = i & 15;
            *(uint4*)(dst + r * TROW + c8 * 16) = src[i];
        }
    }
    if (tid < 128) { b1s[tid] = b1[tid]; b2s[tid] = b2[tid]; }

    // stage z -> A hi/lo
    for (int i = tid; i < 4096; i += MLP_THREADS) {
        int r = i >> 5, c4 = i & 31;
        float4 v = make_float4(0.f, 0.f, 0.f, 0.f);
        if (row0 + r < N_NODES)
            v = *(const float4*)(zin + (size_t)(row0 + r) * NHID + c4 * 4);
        __nv_bfloat16 h0 = __float2bfloat16_rn(v.x), h1 = __float2bfloat16_rn(v.y);
        __nv_bfloat16 h2 = __float2bfloat16_rn(v.z), h3 = __float2bfloat16_rn(v.w);
        uint2 hv = make_uint2(pack_bf16(h0, h1), pack_bf16(h2, h3));
        uint2 lv = make_uint2(
            pack_bf16(__float2bfloat16_rn(v.x - __bfloat162float(h0)),
                      __float2bfloat16_rn(v.y - __bfloat162float(h1))),
            pack_bf16(__float2bfloat16_rn(v.z - __bfloat162float(h2)),
                      __float2bfloat16_rn(v.w - __bfloat162float(h3))));
        *(uint2*)(smem + SM_AHI + r * TROW + c4 * 8) = hv;
        *(uint2*)(smem + SM_ALO + r * TROW + c4 * 8) = lv;
    }
    __syncthreads();

    const int mg = wid >> 1, ng = wid & 1;
    const int cpair = 2 * (lane & 3);
    float acc[8][4];

    // ---- GEMM1: t = relu(z @ W1^T + b1) ----
#pragma unroll
    for (int nt = 0; nt < 8; nt++) {
        int col = ng * 64 + (nt >> 1) * 16 + (nt & 1) * 8 + cpair;
        float bb0 = b1s[col], bb1 = b1s[col + 1];
        acc[nt][0] = bb0; acc[nt][1] = bb1;
        acc[nt][2] = bb0; acc[nt][3] = bb1;
    }
    gemm128(sbase, SM_W1HI, SM_W1LO, wid, lane, acc);

    __syncthreads();   // all warps done reading A tiles

    // epilogue1: relu + hi/lo re-split into A tiles
    {
        int rA = mg * 16 + (lane >> 2);
#pragma unroll
        for (int nt = 0; nt < 8; nt++) {
            int col = ng * 64 + (nt >> 1) * 16 + (nt & 1) * 8 + cpair;
            float v0 = fmaxf(acc[nt][0], 0.f), v1 = fmaxf(acc[nt][1], 0.f);
            float v2 = fmaxf(acc[nt][2], 0.f), v3 = fmaxf(acc[nt][3], 0.f);
            __nv_bfloat16 h0 = __float2bfloat16_rn(v0), h1 = __float2bfloat16_rn(v1);
            __nv_bfloat16 h2 = __float2bfloat16_rn(v2), h3 = __float2bfloat16_rn(v3);
            *(unsigned*)(smem + SM_AHI + rA * TROW + col * 2) = pack_bf16(h0, h1);
            *(unsigned*)(smem + SM_AHI + (rA + 8) * TROW + col * 2) = pack_bf16(h2, h3);
            *(unsigned*)(smem + SM_ALO + rA * TROW + col * 2) =
                pack_bf16(__float2bfloat16_rn(v0 - __bfloat162float(h0)),
                          __float2bfloat16_rn(v1 - __bfloat162float(h1)));
            *(unsigned*)(smem + SM_ALO + (rA + 8) * TROW + col * 2) =
                pack_bf16(__float2bfloat16_rn(v2 - __bfloat162float(h2)),
                          __float2bfloat16_rn(v3 - __bfloat162float(h3)));
        }
    }
    __syncthreads();

    // ---- GEMM2: out = relu(t @ W2^T + b2) ----
#pragma unroll
    for (int nt = 0; nt < 8; nt++) {
        int col = ng * 64 + (nt >> 1) * 16 + (nt & 1) * 8 + cpair;
        float bb0 = b2s[col], bb1 = b2s[col + 1];
        acc[nt][0] = bb0; acc[nt][1] = bb1;
        acc[nt][2] = bb0; acc[nt][3] = bb1;
    }
    gemm128(sbase, SM_W2HI, SM_W2LO, wid, lane, acc);

    // epilogue2: relu + store (float2 pairs)
    {
        int grA = row0 + mg * 16 + (lane >> 2);
        int grB = grA + 8;
#pragma unroll
        for (int nt = 0; nt < 8; nt++) {
            int col = ng * 64 + (nt >> 1) * 16 + (nt & 1) * 8 + cpair;
            if (grA < N_NODES)
                *(float2*)(hout + (size_t)grA * NHID + col) =
                    make_float2(fmaxf(acc[nt][0], 0.f), fmaxf(acc[nt][1], 0.f));
            if (grB < N_NODES)
                *(float2*)(hout + (size_t)grB * NHID + col) =
                    make_float2(fmaxf(acc[nt][2], 0.f), fmaxf(acc[nt][3], 0.f));
        }
    }
}

// ---------------- pooling + log_softmax --------------------------------------
__global__ void pool_zero_kernel() {
    int i = blockIdx.x * blockDim.x + threadIdx.x;
    if (i < N_GRAPHS * NHID) g_pool[i] = 0.f;
}
__global__ void pool_kernel(const float* __restrict__ h,
                            const void* __restrict__ batch_raw) {
    int t = blockIdx.x * blockDim.x + threadIdx.x;
    int n = t >> 5;
    int c = (t & 31) << 2;
    int g = load_idx(batch_raw, n, g_idx64);
    float4 v = *(const float4*)(h + (size_t)n * NHID + c);
    red_add_v4(g_pool + g * NHID + c, v);
}
__global__ void lsm_kernel(float* __restrict__ out) {
    int r = blockIdx.x;
    int c = threadIdx.x;
    int w = c >> 5, lane = c & 31;
    __shared__ float smax[4], ssum[4];
    float v = g_pool[r * NHID + c];
    float m = v;
#pragma unroll
    for (int off = 16; off > 0; off >>= 1)
        m = fmaxf(m, __shfl_xor_sync(0xffffffffu, m, off));
    if (lane == 0) smax[w] = m;
    __syncthreads();
    m = fmaxf(fmaxf(smax[0], smax[1]), fmaxf(smax[2], smax[3]));
    float e = expf(v - m);
    float s = e;
#pragma unroll
    for (int off = 16; off > 0; off >>= 1)
        s += __shfl_xor_sync(0xffffffffu, s, off);
    if (lane == 0) ssum[w] = s;
    __syncthreads();
    s = ssum[0] + ssum[1] + ssum[2] + ssum[3];
    out[r * NHID + c] = (v - m) - logf(s);
}

// ---------------- launch -----------------------------------------------------
extern "C" void kernel_launch(void* const* d_in, const int* in_sizes, int n_in,
                              void* d_out, int out_size) {
    const float* x     = nullptr;
    const void*  ei    = nullptr;
    const void*  batch = nullptr;
    const float *W1 = nullptr, *b1 = nullptr, *W2 = nullptr, *b2 = nullptr;
    for (int i = 0; i < n_in; i++) {
        int sz = in_sizes[i];
        if (sz == N_NODES * NHID)            x = (const float*)d_in[i];
        else if (sz == 2 * N_EDGES)          ei = d_in[i];
        else if (sz == N_NODES)              batch = d_in[i];
        else if (sz == NLAYER * NHID * NHID) { if (!W1) W1 = (const float*)d_in[i]; else W2 = (const float*)d_in[i]; }
        else if (sz == NLAYER * NHID)        { if (!b1) b1 = (const float*)d_in[i]; else b2 = (const float*)d_in[i]; }
    }
    float* out = (float*)d_out;

    float *zp = nullptr, *hp = nullptr;
    unsigned short* wb = nullptr;
    cudaGetSymbolAddress((void**)&zp, g_z);
    cudaGetSymbolAddress((void**)&hp, g_h);
    cudaGetSymbolAddress((void**)&wb, g_wb);

    cudaFuncSetAttribute(mlp_mma_kernel, cudaFuncAttributeMaxDynamicSharedMemorySize, MMA_SMEM_BYTES);

    const int scan_blocks = (N_NODES + 1023) / 1024;
    const int edge_blocks = (N_EDGES + 255) / 256;
    const int node_blocks = (N_NODES + 255) / 256;
    const int agg_blocks  = (N_NODES * 32 + 255) / 256;
    const int mlp_blocks  = (N_NODES + 127) / 128;   // 782
    const int pool_blocks = (N_NODES * 32) / 256;

    detect_kernel<<<1, 32>>>((const int*)ei);
    deg_zero_kernel<<<node_blocks, 256>>>();
    hist_kernel<<<edge_blocks, 256>>>(ei);
    scan1_kernel<<<scan_blocks, 1024>>>();
    scan2_kernel<<<1, 128>>>(scan_blocks);
    scan3_kernel<<<node_blocks, 256>>>();
    fill_kernel<<<edge_blocks, 256>>>(ei);
    wconv_kernel<<<6, 256>>>(W1, W2);

    const float* hin = x;
    for (int l = 0; l < NLAYER; l++) {
        gin_agg_kernel<<<agg_blocks, 256>>>(hin, zp);
        mlp_mma_kernel<<<mlp_blocks, MLP_THREADS, MMA_SMEM_BYTES>>>(
            zp, wb + (size_t)l * 4 * 16384, b1 + l * NHID, b2 + l * NHID, hp);
        hin = hp;
    }

    pool_zero_kernel<<<(N_GRAPHS * NHID + 255) / 256, 256>>>();
    pool_kernel<<<pool_blocks, 256>>>(hp, batch);
    lsm_kernel<<<N_GRAPHS, NHID>>>(out);
}

// round 12
// speedup vs baseline: 2.5463x; 1.2496x over previous
#include <cuda_runtime.h>
#include <cuda_bf16.h>
#include <cstdint>

#define N_NODES 100000
#define N_EDGES 1600000
#define N_GRAPHS 512
#define NHID 128
#define NLAYER 3

typedef unsigned long long ull;

// ---------------- scratch (static device arrays; no allocation) -------------
__device__ __align__(16) float g_z[(size_t)N_NODES * NHID];   // z = h + agg
__device__ __align__(16) float g_h[(size_t)N_NODES * NHID];   // layer out
__device__ __align__(16) float g_pool[N_GRAPHS * NHID];
__device__ int g_idx64;
__device__ int g_deg[N_NODES];
__device__ int g_rowoff[N_NODES + 1];
__device__ int g_csr_src[N_EDGES];
__device__ int g_bsum[128];
// bf16 weights, plain row-major [layer][mat][part(hi,lo)][128*128]
__device__ __align__(16) unsigned short g_wb[12 * 16384];

// ---------------- generic helpers -------------------------------------------
__device__ __forceinline__ void red_add_v4(float* addr, float4 v) {
    asm volatile("red.global.add.v4.f32 [%0], {%1,%2,%3,%4};"
                 :: "l"(addr), "f"(v.x), "f"(v.y), "f"(v.z), "f"(v.w)
                 : "memory");
}
__device__ __forceinline__ int load_idx(const void* raw, int i, int idx64) {
    return idx64 ? (int)((const long long*)raw)[i] : ((const int*)raw)[i];
}
__device__ __forceinline__ uint32_t smem_u32(const void* p) {
    uint32_t a;
    asm("{ .reg .u64 t; cvta.to.shared.u64 t, %1; cvt.u32.u64 %0, t; }"
        : "=r"(a) : "l"(p));
    return a;
}
__device__ __forceinline__ unsigned pack_bf16(__nv_bfloat16 a, __nv_bfloat16 b) {
    return (unsigned)__bfloat16_as_ushort(a) | ((unsigned)__bfloat16_as_ushort(b) << 16);
}

// ---------------- mma.sync helpers (sm_80+ portable) -------------------------
__device__ __forceinline__ void ldm_x4(uint32_t r[4], uint32_t addr) {
    asm volatile("ldmatrix.sync.aligned.m8n8.x4.shared.b16 {%0,%1,%2,%3}, [%4];"
                 : "=r"(r[0]), "=r"(r[1]), "=r"(r[2]), "=r"(r[3]) : "r"(addr));
}
__device__ __forceinline__ void mma_bf16(float acc[4], const uint32_t a[4], const uint32_t b[2]) {
    asm volatile("mma.sync.aligned.m16n8k16.row.col.f32.bf16.bf16.f32 "
                 "{%0,%1,%2,%3}, {%4,%5,%6,%7}, {%8,%9}, {%0,%1,%2,%3};"
                 : "+f"(acc[0]), "+f"(acc[1]), "+f"(acc[2]), "+f"(acc[3])
                 : "r"(a[0]), "r"(a[1]), "r"(a[2]), "r"(a[3]),
                   "r"(b[0]), "r"(b[1]));
}
__device__ __forceinline__ void cpasync16(uint32_t dst, const void* src) {
    asm volatile("cp.async.cg.shared.global [%0], [%1], 16;"
                 :: "r"(dst), "l"(src) : "memory");
}
#define CP_COMMIT() asm volatile("cp.async.commit_group;" ::: "memory")
#define CP_WAIT0()  asm volatile("cp.async.wait_group 0;" ::: "memory")

// ---------------- index-width detection --------------------------------------
__global__ void detect_kernel(const int* __restrict__ ei_raw) {
    if (threadIdx.x == 0) {
        int odd = 0;
        for (int i = 0; i < 64; i++) odd |= ei_raw[2 * i + 1];
        g_idx64 = (odd == 0) ? 1 : 0;
    }
}

// ---------------- CSR build ---------------------------------------------------
__global__ void deg_zero_kernel() {
    int i = blockIdx.x * blockDim.x + threadIdx.x;
    if (i < N_NODES) g_deg[i] = 0;
}
__global__ void hist_kernel(const void* __restrict__ ei_raw) {
    int e = blockIdx.x * blockDim.x + threadIdx.x;
    if (e < N_EDGES) atomicAdd(&g_deg[load_idx(ei_raw, N_EDGES + e, g_idx64)], 1);
}
__global__ void scan1_kernel() {
    __shared__ int wsum[32];
    int b = blockIdx.x, t = threadIdx.x;
    int gi = b * 1024 + t;
    int v = (gi < N_NODES) ? g_deg[gi] : 0;
    int lane = t & 31, w = t >> 5;
    int s = v;
#pragma unroll
    for (int o = 1; o < 32; o <<= 1) {
        int u = __shfl_up_sync(0xffffffffu, s, o);
        if (lane >= o) s += u;
    }
    if (lane == 31) wsum[w] = s;
    __syncthreads();
    if (w == 0) {
        int ws = wsum[lane];
#pragma unroll
        for (int o = 1; o < 32; o <<= 1) {
            int u = __shfl_up_sync(0xffffffffu, ws, o);
            if (lane >= o) ws += u;
        }
        wsum[lane] = ws;
    }
    __syncthreads();
    int excl = s - v + (w > 0 ? wsum[w - 1] : 0);
    if (gi < N_NODES) g_rowoff[gi] = excl;
    if (t == 1023) g_bsum[b] = excl + v;
}
__global__ void scan2_kernel(int nblocks) {
    if (threadIdx.x == 0) {
        int acc = 0;
        for (int i = 0; i < nblocks; i++) { int t = g_bsum[i]; g_bsum[i] = acc; acc += t; }
        g_rowoff[N_NODES] = N_EDGES;
    }
}
__global__ void scan3_kernel() {
    int i = blockIdx.x * blockDim.x + threadIdx.x;
    if (i < N_NODES) { g_rowoff[i] += g_bsum[i >> 10]; g_deg[i] = 0; }
}
__global__ void fill_kernel(const void* __restrict__ ei_raw) {
    int e = blockIdx.x * blockDim.x + threadIdx.x;
    if (e < N_EDGES) {
        int idx64 = g_idx64;
        int s = load_idx(ei_raw, e, idx64);
        int d = load_idx(ei_raw, N_EDGES + e, idx64);
        g_csr_src[g_rowoff[d] + atomicAdd(&g_deg[d], 1)] = s;
    }
}

// ---------------- aggregation: z = h + sum_{src in N(dst)} h[src] ------------
__global__ __launch_bounds__(256, 8)
void gin_agg_kernel(const float* __restrict__ h, float* __restrict__ z) {
    int gw = (blockIdx.x * blockDim.x + threadIdx.x) >> 5;
    if (gw >= N_NODES) return;
    int lane = threadIdx.x & 31;
    int c = lane << 2;
    float4 acc = *(const float4*)(h + (size_t)gw * NHID + c);
    int beg = g_rowoff[gw], end = g_rowoff[gw + 1];
    for (int i = beg; i < end; i += 32) {
        int cnt = min(32, end - i);
        int s = (lane < cnt) ? g_csr_src[i + lane] : 0;
        for (int j = 0; j < cnt; j++) {
            int sj = __shfl_sync(0xffffffffu, s, j);
            float4 v = *(const float4*)(h + (size_t)sj * NHID + c);
            acc.x += v.x; acc.y += v.y; acc.z += v.z; acc.w += v.w;
        }
    }
    *(float4*)(z + (size_t)gw * NHID + c) = acc;
}

// ---------------- weight conversion (fp32 -> plain bf16 hi/lo) ---------------
__global__ void wconv_kernel(const float* __restrict__ W1, const float* __restrict__ W2) {
    int l = blockIdx.x >> 1, m = blockIdx.x & 1;
    const float* W = (m == 0 ? W1 : W2) + l * NHID * NHID;
    unsigned short* hi = g_wb + (size_t)((l * 2 + m) * 2 + 0) * 16384;
    unsigned short* lo = g_wb + (size_t)((l * 2 + m) * 2 + 1) * 16384;
    for (int i = threadIdx.x; i < 16384; i += blockDim.x) {
        float v = W[i];
        __nv_bfloat16 h = __float2bfloat16_rn(v);
        __nv_bfloat16 lw = __float2bfloat16_rn(v - __bfloat162float(h));
        hi[i] = __bfloat16_as_ushort(h);
        lo[i] = __bfloat16_as_ushort(lw);
    }
}

// ---------------- persistent HMMA fused MLP ----------------------------------
// 148 CTAs x 512 thr; each CTA loops over 64-row tiles (stride gridDim).
// Weights staged ONCE per CTA; next tile's z prefetched via cp.async during
// the GEMMs. bf16 hi/lo split (3 mma chains). 16 warps, warp tile 16x32.
#define TROW 272
#define WTILE_B (128 * TROW)            // 34816 (weight tile, 128 rows)
#define ATILE_B (64 * TROW)             // 17408 (A tile, 64 rows)
#define SM_W1HI 0
#define SM_W1LO (1 * WTILE_B)
#define SM_W2HI (2 * WTILE_B)
#define SM_W2LO (3 * WTILE_B)
#define SM_AHI  (4 * WTILE_B)                     // 139264
#define SM_ALO  (4 * WTILE_B + ATILE_B)           // 156672
#define SM_ZRAW (4 * WTILE_B + 2 * ATILE_B)       // 174080 (64 rows x 512 B)
#define SM_B1   (SM_ZRAW + 32768)                 // 206848
#define SM_B2   (SM_B1 + 512)
#define MMA_SMEM_BYTES (SM_B2 + 512 + 256)        // ~208 KB
#define MLP_THREADS 512
#define NTILES ((N_NODES + 63) / 64)              // 1563

__device__ __forceinline__ void prefetch_z(uint32_t sbase, const float* __restrict__ z,
                                           int tile, int tid) {
    int row0 = tile * 64;
#pragma unroll
    for (int k = 0; k < 4; k++) {
        int i = tid + k * MLP_THREADS;            // 2048 chunks of 16 B
        int r = i >> 5, c16 = i & 31;
        int row = row0 + r;
        if (row < N_NODES)
            cpasync16(sbase + SM_ZRAW + (uint32_t)i * 16,
                      z + (size_t)row * NHID + c16 * 4);
    }
}

__device__ __forceinline__ void gemm64(uint32_t sbase, uint32_t whi, uint32_t wlo,
                                       int mg, int ng, int lane, float acc[4][4]) {
    const uint32_t a0 = sbase + (uint32_t)(mg * 16 + (lane & 15)) * TROW
                      + (((uint32_t)lane >> 4) << 4);
    const uint32_t wb0 = (uint32_t)(ng * 32 + ((lane >> 4) & 1) * 8 + (lane & 7)) * TROW
                       + ((((uint32_t)lane >> 3) & 1) << 4);
#pragma unroll
    for (int kk = 0; kk < 8; kk++) {
        const uint32_t ka = kk * 32;
        uint32_t ahi[4], alo[4];
        ldm_x4(ahi, a0 + SM_AHI + ka);
        ldm_x4(alo, a0 + SM_ALO + ka);
#pragma unroll
        for (int p = 0; p < 2; p++) {
            uint32_t wh[4], wl[4];
            const uint32_t ba = sbase + wb0 + (uint32_t)(p * 16) * TROW + ka;
            ldm_x4(wh, ba + whi);
            ldm_x4(wl, ba + wlo);
            mma_bf16(acc[2 * p],     ahi, wh);
            mma_bf16(acc[2 * p],     ahi, wl);
            mma_bf16(acc[2 * p],     alo, wh);
            mma_bf16(acc[2 * p + 1], ahi, wh + 2);
            mma_bf16(acc[2 * p + 1], ahi, wl + 2);
            mma_bf16(acc[2 * p + 1], alo, wh + 2);
        }
    }
}

__global__ __launch_bounds__(MLP_THREADS, 1)
void mlp_mma_kernel(const float* __restrict__ zin,
                    const unsigned short* __restrict__ wb,   // w1hi,w1lo,w2hi,w2lo
                    const float* __restrict__ b1, const float* __restrict__ b2,
                    float* __restrict__ hout) {
    extern __shared__ char smem[];
    const uint32_t sbase = smem_u32(smem);
    const int tid = threadIdx.x;
    const int wid = tid >> 5;
    const int lane = tid & 31;
    const int mg = wid >> 2;          // 0..3 -> rows mg*16..+15
    const int ng = wid & 3;           // 0..3 -> cols ng*32..+31
    const int cpair = 2 * (lane & 3);
    float* b1s = (float*)(smem + SM_B1);
    float* b2s = (float*)(smem + SM_B2);

    int tile = blockIdx.x;
    if (tile < NTILES) prefetch_z(sbase, zin, tile, tid);
    CP_COMMIT();

    // stage all 4 weight tiles once (pad 128->136 bf16 rows)
#pragma unroll
    for (int t = 0; t < 4; t++) {
        const uint4* src = (const uint4*)(wb + (size_t)t * 16384);
        char* dst = smem + t * WTILE_B;
        for (int i = tid; i < 2048; i += MLP_THREADS) {
            int r = i >> 4, c8 = i & 15;
            *(uint4*)(dst + r * TROW + c8 * 16) = src[i];
        }
    }
    if (tid < 128) { b1s[tid] = b1[tid]; b2s[tid] = b2[tid]; }
    __syncthreads();

    for (; tile < NTILES; tile += gridDim.x) {
        const int row0 = tile * 64;
        const int next = tile + gridDim.x;

        CP_WAIT0();
        __syncthreads();   // all threads' cp.async data visible

        // convert zraw -> A hi/lo tiles
        for (int i = tid; i < 4096; i += MLP_THREADS) {   // 64 rows x 64 col-pairs
            int r = i >> 6, cp = i & 63, col = cp * 2;
            float2 v = make_float2(0.f, 0.f);
            if (row0 + r < N_NODES)
                v = *(const float2*)(smem + SM_ZRAW + r * 512 + col * 4);
            __nv_bfloat16 h0 = __float2bfloat16_rn(v.x), h1 = __float2bfloat16_rn(v.y);
            *(unsigned*)(smem + SM_AHI + r * TROW + col * 2) = pack_bf16(h0, h1);
            *(unsigned*)(smem + SM_ALO + r * TROW + col * 2) =
                pack_bf16(__float2bfloat16_rn(v.x - __bfloat162float(h0)),
                          __float2bfloat16_rn(v.y - __bfloat162float(h1)));
        }
        __syncthreads();   // A ready; zraw free

        if (next < NTILES) prefetch_z(sbase, zin, next, tid);
        CP_COMMIT();

        float acc[4][4];

        // ---- GEMM1: t = relu(z @ W1^T + b1) ----
#pragma unroll
        for (int nt = 0; nt < 4; nt++) {
            int col = ng * 32 + (nt >> 1) * 16 + (nt & 1) * 8 + cpair;
            float bb0 = b1s[col], bb1 = b1s[col + 1];
            acc[nt][0] = bb0; acc[nt][1] = bb1;
            acc[nt][2] = bb0; acc[nt][3] = bb1;
        }
        gemm64(sbase, SM_W1HI, SM_W1LO, mg, ng, lane, acc);
        __syncthreads();   // all warps done reading A

        // epilogue1: relu + hi/lo re-split into A tiles
        {
            int rA = mg * 16 + (lane >> 2);
#pragma unroll
            for (int nt = 0; nt < 4; nt++) {
                int col = ng * 32 + (nt >> 1) * 16 + (nt & 1) * 8 + cpair;
                float v0 = fmaxf(acc[nt][0], 0.f), v1 = fmaxf(acc[nt][1], 0.f);
                float v2 = fmaxf(acc[nt][2], 0.f), v3 = fmaxf(acc[nt][3], 0.f);
                __nv_bfloat16 h0 = __float2bfloat16_rn(v0), h1 = __float2bfloat16_rn(v1);
                __nv_bfloat16 h2 = __float2bfloat16_rn(v2), h3 = __float2bfloat16_rn(v3);
                *(unsigned*)(smem + SM_AHI + rA * TROW + col * 2) = pack_bf16(h0, h1);
                *(unsigned*)(smem + SM_AHI + (rA + 8) * TROW + col * 2) = pack_bf16(h2, h3);
                *(unsigned*)(smem + SM_ALO + rA * TROW + col * 2) =
                    pack_bf16(__float2bfloat16_rn(v0 - __bfloat162float(h0)),
                              __float2bfloat16_rn(v1 - __bfloat162float(h1)));
                *(unsigned*)(smem + SM_ALO + (rA + 8) * TROW + col * 2) =
                    pack_bf16(__float2bfloat16_rn(v2 - __bfloat162float(h2)),
                              __float2bfloat16_rn(v3 - __bfloat162float(h3)));
            }
        }
        __syncthreads();

        // ---- GEMM2: out = relu(t @ W2^T + b2) ----
#pragma unroll
        for (int nt = 0; nt < 4; nt++) {
            int col = ng * 32 + (nt >> 1) * 16 + (nt & 1) * 8 + cpair;
            float bb0 = b2s[col], bb1 = b2s[col + 1];
            acc[nt][0] = bb0; acc[nt][1] = bb1;
            acc[nt][2] = bb0; acc[nt][3] = bb1;
        }
        gemm64(sbase, SM_W2HI, SM_W2LO, mg, ng, lane, acc);

        // epilogue2: relu + store (float2 pairs)
        {
            int grA = row0 + mg * 16 + (lane >> 2);
            int grB = grA + 8;
#pragma unroll
            for (int nt = 0; nt < 4; nt++) {
                int col = ng * 32 + (nt >> 1) * 16 + (nt & 1) * 8 + cpair;
                if (grA < N_NODES)
                    *(float2*)(hout + (size_t)grA * NHID + col) =
                        make_float2(fmaxf(acc[nt][0], 0.f), fmaxf(acc[nt][1], 0.f));
                if (grB < N_NODES)
                    *(float2*)(hout + (size_t)grB * NHID + col) =
                        make_float2(fmaxf(acc[nt][2], 0.f), fmaxf(acc[nt][3], 0.f));
            }
        }
        __syncthreads();   // A reads done before next convert overwrites
    }
}

// ---------------- pooling + log_softmax --------------------------------------
__global__ void pool_zero_kernel() {
    int i = blockIdx.x * blockDim.x + threadIdx.x;
    if (i < N_GRAPHS * NHID) g_pool[i] = 0.f;
}
__global__ void pool_kernel(const float* __restrict__ h,
                            const void* __restrict__ batch_raw) {
    int t = blockIdx.x * blockDim.x + threadIdx.x;
    int n = t >> 5;
    int c = (t & 31) << 2;
    int g = load_idx(batch_raw, n, g_idx64);
    float4 v = *(const float4*)(h + (size_t)n * NHID + c);
    red_add_v4(g_pool + g * NHID + c, v);
}
__global__ void lsm_kernel(float* __restrict__ out) {
    int r = blockIdx.x;
    int c = threadIdx.x;
    int w = c >> 5, lane = c & 31;
    __shared__ float smax[4], ssum[4];
    float v = g_pool[r * NHID + c];
    float m = v;
#pragma unroll
    for (int off = 16; off > 0; off >>= 1)
        m = fmaxf(m, __shfl_xor_sync(0xffffffffu, m, off));
    if (lane == 0) smax[w] = m;
    __syncthreads();
    m = fmaxf(fmaxf(smax[0], smax[1]), fmaxf(smax[2], smax[3]));
    float e = expf(v - m);
    float s = e;
#pragma unroll
    for (int off = 16; off > 0; off >>= 1)
        s += __shfl_xor_sync(0xffffffffu, s, off);
    if (lane == 0) ssum[w] = s;
    __syncthreads();
    s = ssum[0] + ssum[1] + ssum[2] + ssum[3];
    out[r * NHID + c] = (v - m) - logf(s);
}

// ---------------- launch -----------------------------------------------------
extern "C" void kernel_launch(void* const* d_in, const int* in_sizes, int n_in,
                              void* d_out, int out_size) {
    const float* x     = nullptr;
    const void*  ei    = nullptr;
    const void*  batch = nullptr;
    const float *W1 = nullptr, *b1 = nullptr, *W2 = nullptr, *b2 = nullptr;
    for (int i = 0; i < n_in; i++) {
        int sz = in_sizes[i];
        if (sz == N_NODES * NHID)            x = (const float*)d_in[i];
        else if (sz == 2 * N_EDGES)          ei = d_in[i];
        else if (sz == N_NODES)              batch = d_in[i];
        else if (sz == NLAYER * NHID * NHID) { if (!W1) W1 = (const float*)d_in[i]; else W2 = (const float*)d_in[i]; }
        else if (sz == NLAYER * NHID)        { if (!b1) b1 = (const float*)d_in[i]; else b2 = (const float*)d_in[i]; }
    }
    float* out = (float*)d_out;

    float *zp = nullptr, *hp = nullptr;
    unsigned short* wb = nullptr;
    cudaGetSymbolAddress((void**)&zp, g_z);
    cudaGetSymbolAddress((void**)&hp, g_h);
    cudaGetSymbolAddress((void**)&wb, g_wb);

    cudaFuncSetAttribute(mlp_mma_kernel, cudaFuncAttributeMaxDynamicSharedMemorySize, MMA_SMEM_BYTES);

    const int scan_blocks = (N_NODES + 1023) / 1024;
    const int edge_blocks = (N_EDGES + 255) / 256;
    const int node_blocks = (N_NODES + 255) / 256;
    const int agg_blocks  = (N_NODES * 32 + 255) / 256;
    const int pool_blocks = (N_NODES * 32) / 256;

    detect_kernel<<<1, 32>>>((const int*)ei);
    deg_zero_kernel<<<node_blocks, 256>>>();
    hist_kernel<<<edge_blocks, 256>>>(ei);
    scan1_kernel<<<scan_blocks, 1024>>>();
    scan2_kernel<<<1, 128>>>(scan_blocks);
    scan3_kernel<<<node_blocks, 256>>>();
    fill_kernel<<<edge_blocks, 256>>>(ei);
    wconv_kernel<<<6, 256>>>(W1, W2);

    const float* hin = x;
    for (int l = 0; l < NLAYER; l++) {
        gin_agg_kernel<<<agg_blocks, 256>>>(hin, zp);
        mlp_mma_kernel<<<148, MLP_THREADS, MMA_SMEM_BYTES>>>(
            zp, wb + (size_t)l * 4 * 16384, b1 + l * NHID, b2 + l * NHID, hp);
        hin = hp;
    }

    pool_zero_kernel<<<(N_GRAPHS * NHID + 255) / 256, 256>>>();
    pool_kernel<<<pool_blocks, 256>>>(hp, batch);
    lsm_kernel<<<N_GRAPHS, NHID>>>(out);
}